// round 7
// baseline (speedup 1.0000x reference)
#include <cuda_runtime.h>
#include <math.h>

#define NB   16
#define SEQ  1024
#define CH   64
#define NC   5
#define MD   96

// ---------------- scratch (device globals; no allocation) ----------------
__device__ float g_w1[NB*SEQ*NC];
__device__ float g_w2[NB*NC*SEQ];
__device__ float g_cf[NB*SEQ*CH];
__device__ float g_pool[NB*16*NC*64];   // pooling partials [b][st][n*64+c]
__device__ float g_q [NB*4*SEQ*64];   // [b][h][s][d']  (d pair-interleaved)
__device__ float g_k [NB*4*SEQ*64];   // [b][h][s][d']  (d pair-interleaved)
__device__ float g_v [NB*4*SEQ*64];   // [b][h][d][s]   (TRANSPOSED)
__device__ float g_o [NB*4*SEQ*64];

// ---------------- helpers ----------------
__device__ __forceinline__ float tf32r(float x){
    unsigned u; asm("cvt.rna.tf32.f32 %0, %1;" : "=r"(u) : "f"(x));
    return __uint_as_float(u);
}
__device__ __forceinline__ unsigned tf32u(float x){
    unsigned u; asm("cvt.rna.tf32.f32 %0, %1;" : "=r"(u) : "f"(x));
    return u;
}
__device__ __forceinline__ float fex2(float x){
    float r; asm("ex2.approx.ftz.f32 %0, %1;" : "=f"(r) : "f"(x));
    return r;
}
__device__ __forceinline__ void cp16(void* dst, const void* src){
    unsigned d = (unsigned)__cvta_generic_to_shared(dst);
    asm volatile("cp.async.cg.shared.global [%0], [%1], 16;" :: "r"(d), "l"(src));
}
#define CP_COMMIT asm volatile("cp.async.commit_group;")
#define CP_WAIT1  asm volatile("cp.async.wait_group 1;")

#define MMA_TF32(c0,c1,c2,c3,a0,a1,a2,a3,b0,b1)                               \
  asm volatile("mma.sync.aligned.m16n8k8.row.col.f32.tf32.tf32.f32 "          \
    "{%0,%1,%2,%3}, {%4,%5,%6,%7}, {%8,%9}, {%0,%1,%2,%3};"                   \
    : "+f"(c0),"+f"(c1),"+f"(c2),"+f"(c3)                                     \
    : "r"(a0),"r"(a1),"r"(a2),"r"(a3),"r"(b0),"r"(b1))

// ================= Kernel A: weight = xt@wb_w, both softmaxes =============
__global__ __launch_bounds__(1024) void kA(const float* __restrict__ x,
                                           const float* __restrict__ wbw,
                                           const float* __restrict__ wbb)
{
    const int b = blockIdx.x, s = threadIdx.x;
    __shared__ float ws[CH*NC];
    __shared__ float red[32*NC];
    __shared__ float Mx[NC], Sx[NC];
    if (s < CH*NC) ws[s] = wbw[s];
    __syncthreads();

    const float* xb = x + b*(CH*SEQ) + s;
    float w[NC];
    #pragma unroll
    for (int n=0;n<NC;n++) w[n] = wbb[n];
    #pragma unroll 8
    for (int c=0;c<CH;c++){
        float xv = xb[c<<10];
        #pragma unroll
        for (int n=0;n<NC;n++) w[n] = fmaf(xv, ws[c*NC+n], w[n]);
    }

    {
        float mx = w[0];
        #pragma unroll
        for (int n=1;n<NC;n++) mx = fmaxf(mx, w[n]);
        float e[NC], ssum = 0.f;
        #pragma unroll
        for (int n=0;n<NC;n++){ e[n] = __expf(w[n]-mx); ssum += e[n]; }
        float inv = 1.f/ssum;
        float* w1p = g_w1 + b*(SEQ*NC) + s*NC;
        #pragma unroll
        for (int n=0;n<NC;n++) w1p[n] = e[n]*inv;
    }

    const int lane = s & 31, wid = s >> 5;
    float r5[NC];
    #pragma unroll
    for (int n=0;n<NC;n++) r5[n] = w[n];
    #pragma unroll
    for (int off=16; off; off>>=1)
        #pragma unroll
        for (int n=0;n<NC;n++) r5[n] = fmaxf(r5[n], __shfl_xor_sync(0xffffffffu, r5[n], off));
    if (lane==0){
        #pragma unroll
        for (int n=0;n<NC;n++) red[wid*NC+n] = r5[n];
    }
    __syncthreads();
    if (wid==0){
        #pragma unroll
        for (int n=0;n<NC;n++) r5[n] = red[lane*NC+n];
        #pragma unroll
        for (int off=16; off; off>>=1)
            #pragma unroll
            for (int n=0;n<NC;n++) r5[n] = fmaxf(r5[n], __shfl_xor_sync(0xffffffffu, r5[n], off));
        if (lane==0){
            #pragma unroll
            for (int n=0;n<NC;n++) Mx[n] = r5[n];
        }
    }
    __syncthreads();
    float e2[NC];
    #pragma unroll
    for (int n=0;n<NC;n++){ e2[n] = __expf(w[n]-Mx[n]); r5[n] = e2[n]; }
    #pragma unroll
    for (int off=16; off; off>>=1)
        #pragma unroll
        for (int n=0;n<NC;n++) r5[n] += __shfl_xor_sync(0xffffffffu, r5[n], off);
    if (lane==0){
        #pragma unroll
        for (int n=0;n<NC;n++) red[wid*NC+n] = r5[n];
    }
    __syncthreads();
    if (wid==0){
        #pragma unroll
        for (int n=0;n<NC;n++) r5[n] = red[lane*NC+n];
        #pragma unroll
        for (int off=16; off; off>>=1)
            #pragma unroll
            for (int n=0;n<NC;n++) r5[n] += __shfl_xor_sync(0xffffffffu, r5[n], off);
        if (lane==0){
            #pragma unroll
            for (int n=0;n<NC;n++) Sx[n] = r5[n];
        }
    }
    __syncthreads();
    float* w2p = g_w2 + b*(NC*SEQ) + s;
    #pragma unroll
    for (int n=0;n<NC;n++) w2p[n<<10] = e2[n] / Sx[n];
}

// ====== Kernel P: parallel class pooling partials =========================
// partial[b][st][n][c] = sum_{sl<64} w2[b][n][st*64+sl] * x[b][c][st*64+sl]
__global__ __launch_bounds__(256) void kP(const float* __restrict__ x)
{
    const int st = blockIdx.x, b = blockIdx.y, tid = threadIdx.x;
    __shared__ float xs[64*65];
    __shared__ float w2s[NC*64];
    const int s0 = st*64;
    #pragma unroll
    for (int i=0;i<16;i++){
        int idx = i*256 + tid;
        int c = idx>>6, sl = idx&63;
        xs[c*65+sl] = x[b*65536 + (c<<10) + s0 + sl];
    }
    for (int idx=tid; idx<NC*64; idx+=256)
        w2s[idx] = g_w2[b*5120 + ((idx>>6)<<10) + s0 + (idx&63)];
    __syncthreads();
    for (int idx=tid; idx<NC*64; idx+=256){
        const int n = idx>>6, c = idx&63;
        float a = 0.f;
        #pragma unroll 8
        for (int sl=0; sl<64; sl++) a = fmaf(w2s[n*64+sl], xs[c*65+sl], a);
        g_pool[(b*16+st)*320 + idx] = a;
    }
}

// ====== Kernel B: reduce pooling, MHA1 (5 tokens vs memory), redistribute ==
__global__ __launch_bounds__(512) void kB(
    const float* __restrict__ memory,
    const float* __restrict__ wq, const float* __restrict__ bq,
    const float* __restrict__ wk, const float* __restrict__ bk,
    const float* __restrict__ wv, const float* __restrict__ bv,
    const float* __restrict__ fc, const float* __restrict__ fcb,
    const float* __restrict__ lng, const float* __restrict__ lnb)
{
    const int b = blockIdx.x, tid = threadIdx.x;
    __shared__ float cf1s[NC*64];
    __shared__ float mems[NC*MD];
    __shared__ float qh[NC*MD], kh[NC*MD], vh[NC*64];
    __shared__ float Ssm[NC*NC];
    __shared__ float osm[NC*64];
    __shared__ float projs[NC*64];

    if (tid < 320){
        float acc = 0.f;
        #pragma unroll
        for (int st=0; st<16; st++) acc += g_pool[(b*16+st)*320 + tid];
        cf1s[tid] = acc;
    }
    if (tid < NC*MD) mems[tid] = memory[tid];
    __syncthreads();

    if (tid < 480){
        const int n = tid/96, j = tid - n*96;
        float q = bq[j];
        #pragma unroll
        for (int d=0; d<64; d++) q = fmaf(cf1s[n*64+d], wq[d*96+j], q);
        qh[tid] = q * 0.102062072615966f;
        float kk = bk[j];
        #pragma unroll
        for (int d=0; d<96; d++) kk = fmaf(mems[n*96+d], wk[d*96+j], kk);
        kh[tid] = kk;
    }
    if (tid < 320){
        const int n = tid>>6, c = tid&63;
        float vv = bv[c];
        #pragma unroll
        for (int d=0; d<96; d++) vv = fmaf(mems[n*96+d], wv[d*64+c], vv);
        vh[tid] = vv;
    }
    __syncthreads();

    if (tid < 25){
        const int i = tid/5, j = tid - (tid/5)*5;
        float sv = 0.f;
        #pragma unroll
        for (int d=0; d<96; d++) sv = fmaf(qh[i*96+d], kh[j*96+d], sv);
        Ssm[tid] = sv;
    }
    __syncthreads();
    if (tid < 5){
        float m = Ssm[tid*5];
        #pragma unroll
        for (int j=1;j<5;j++) m = fmaxf(m, Ssm[tid*5+j]);
        float p[5], sum = 0.f;
        #pragma unroll
        for (int j=0;j<5;j++){ p[j] = __expf(Ssm[tid*5+j]-m); sum += p[j]; }
        float inv = 1.f/sum;
        #pragma unroll
        for (int j=0;j<5;j++) Ssm[tid*5+j] = p[j]*inv;
    }
    __syncthreads();
    if (tid < 320){
        const int n = tid>>6, c = tid&63;
        float o = 0.f;
        #pragma unroll
        for (int j=0;j<5;j++) o = fmaf(Ssm[n*5+j], vh[j*64+c], o);
        osm[tid] = o;
    }
    __syncthreads();
    if (tid < 320){
        const int n = tid>>6, c = tid&63;
        float p = fcb[c] + cf1s[tid];
        #pragma unroll
        for (int k=0;k<64;k++) p = fmaf(osm[n*64+k], fc[k*64+c], p);
        projs[tid] = p;
    }
    __syncthreads();
    if (tid < 160){
        const int n = tid>>5, lane = tid&31;
        float v0 = projs[n*64+lane], v1 = projs[n*64+lane+32];
        float sm = v0+v1, sq = v0*v0 + v1*v1;
        #pragma unroll
        for (int off=16; off; off>>=1){
            sm += __shfl_xor_sync(0xffffffffu, sm, off);
            sq += __shfl_xor_sync(0xffffffffu, sq, off);
        }
        float mu = sm*(1.f/64.f);
        float var = sq*(1.f/64.f) - mu*mu;
        float rs = rsqrtf(var + 1e-6f);
        cf1s[n*64+lane]    = (v0-mu)*rs*lng[lane]    + lnb[lane];
        cf1s[n*64+lane+32] = (v1-mu)*rs*lng[lane+32] + lnb[lane+32];
    }
    __syncthreads();
    for (int it=0; it<128; it++){
        int idx = it*512 + tid;
        int s = idx>>6, c = idx&63;
        const float* w1p = g_w1 + b*5120 + s*5;
        float a = 0.f;
        #pragma unroll
        for (int n=0;n<5;n++) a = fmaf(w1p[n], cf1s[n*64+c], a);
        g_cf[b*65536 + idx] = a;
    }
}

// ====== Kernel Cm: fused QKV projection via tf32 mma ======================
// z<2 (Q,K): store with d pair-interleaved within each group of 8.
// z==2 (V):  store transposed [d][s].
__global__ __launch_bounds__(256) void kCm(
    const float* __restrict__ wq, const float* __restrict__ wk, const float* __restrict__ wv,
    const float* __restrict__ bq, const float* __restrict__ bk, const float* __restrict__ bv,
    float* __restrict__ pq, float* __restrict__ pk, float* __restrict__ pv)
{
    extern __shared__ float smc[];
    float* Ast = smc;          // [128][68]
    float* Ws  = smc + 8704;   // [64][136]
    float* bs  = smc + 17408;  // [128]
    const int mt=blockIdx.x, nt=blockIdx.y, z=blockIdx.z;
    const int tid=threadIdx.x, w=tid>>5, lane=tid&31, gid=lane>>2, l4=lane&3;
    const float* W  = (z==0)?wq:((z==1)?wk:wv);
    const float* Bp = (z==0)?bq:((z==1)?bk:bv);
    float*       O  = (z==0)?pq:((z==1)?pk:pv);

    const float* Ap = g_cf + mt*128*64;
    #pragma unroll
    for (int i=0;i<8;i++){
        int idx=i*256+tid, row=idx>>4, c4=(idx&15)*4;
        *(float4*)(Ast + row*68 + c4) = *(const float4*)(Ap + row*64 + c4);
    }
    #pragma unroll
    for (int i=0;i<8;i++){
        int idx=i*256+tid, row=idx>>5, c4=(idx&31)*4;
        *(float4*)(Ws + row*136 + c4) = *(const float4*)(W + row*256 + nt*128 + c4);
    }
    if (tid<128) bs[tid] = Bp[nt*128+tid];
    __syncthreads();

    unsigned af[8][4];
    const int r0 = w*16;
    #pragma unroll
    for (int kk=0;kk<8;kk++){
        af[kk][0]=__float_as_uint(Ast[(r0+gid  )*68 + kk*8   + l4]);
        af[kk][1]=__float_as_uint(Ast[(r0+gid+8)*68 + kk*8   + l4]);
        af[kk][2]=__float_as_uint(Ast[(r0+gid  )*68 + kk*8+4 + l4]);
        af[kk][3]=__float_as_uint(Ast[(r0+gid+8)*68 + kk*8+4 + l4]);
    }
    float c[16][4];
    #pragma unroll
    for (int j=0;j<16;j++){ c[j][0]=c[j][1]=c[j][2]=c[j][3]=0.f; }
    #pragma unroll
    for (int j=0;j<16;j++){
        #pragma unroll
        for (int kk=0;kk<8;kk++){
            unsigned b0=__float_as_uint(Ws[(kk*8+l4  )*136 + j*8+gid]);
            unsigned b1=__float_as_uint(Ws[(kk*8+l4+4)*136 + j*8+gid]);
            MMA_TF32(c[j][0],c[j][1],c[j][2],c[j][3],
                     af[kk][0],af[kk][1],af[kk][2],af[kk][3],b0,b1);
        }
    }
    const int row_lo = mt*128 + r0 + gid;
    const int bidx = row_lo>>10, s_lo = row_lo&1023;
    #pragma unroll
    for (int j=0;j<16;j++){
        int cl = j*8 + 2*l4;
        int col0 = nt*128 + cl;           // even -> col0,col0+1 same head
        int h = col0>>6, d0 = col0&63, d1 = d0+1;
        float* op = O + (((bidx<<2)+h)<<16);
        float v00 = tf32r(c[j][0]+bs[cl]);
        float v01 = tf32r(c[j][1]+bs[cl+1]);
        float v10 = tf32r(c[j][2]+bs[cl]);
        float v11 = tf32r(c[j][3]+bs[cl+1]);
        if (z < 2){
            int dp0 = (d0&56)|((d0&3)<<1)|((d0&4)>>2);
            int dp1 = (d1&56)|((d1&3)<<1)|((d1&4)>>2);
            op[ s_lo   *64 + dp0] = v00;
            op[ s_lo   *64 + dp1] = v01;
            op[(s_lo+8)*64 + dp0] = v10;
            op[(s_lo+8)*64 + dp1] = v11;
        } else {
            op[d0*1024 + s_lo  ] = v00;
            op[d1*1024 + s_lo  ] = v01;
            op[d0*1024 + s_lo+8] = v10;
            op[d1*1024 + s_lo+8] = v11;
        }
    }
}

// ========== Kernel D: tf32 mma flash attention (2 CTAs/SM) ================
__global__ __launch_bounds__(256, 2) void kD()
{
    extern __shared__ float sm[];
    float* KS0 = sm;             // [64][72]
    float* VS0 = sm + 4608;      // [64][72]  (V^T tile: [d][s])
    float* KS1 = sm + 9216;      // [64][72]
    float* VS1 = sm + 13824;     // [64][72]
    float* Qst = sm;             // alias [128][72] (used before K/V loads)

    const int qt=blockIdx.x, h=blockIdx.y, b=blockIdx.z;
    const int tid=threadIdx.x, w=tid>>5, lane=tid&31;
    const int gid=lane>>2, l4=lane&3;
    const int base=((b*4+h)<<16);

    const float* Kg = g_k + base;
    const float* Vg = g_v + base;          // [64 d][1024 s]
    const float* Qg = g_q + base + qt*8192;

    // stage Q scaled by log2(e)/sqrt(64) so softmax uses bare ex2
    const float QSC = 0.125f * 1.4426950408889634f;
    #pragma unroll
    for (int i=0;i<8;i++){
        int idx=i*256+tid, row=idx>>4, c4=(idx&15)*4;
        float4 v = *(const float4*)(Qg + row*64 + c4);
        Qst[row*72+c4+0]=v.x*QSC; Qst[row*72+c4+1]=v.y*QSC;
        Qst[row*72+c4+2]=v.z*QSC; Qst[row*72+c4+3]=v.w*QSC;
    }
    __syncthreads();
    unsigned qf[8][4];
    const int r0 = w*16;
    #pragma unroll
    for (int kk=0;kk<8;kk++){
        float2 lo = *(const float2*)(Qst + (r0+gid  )*72 + kk*8 + 2*l4);
        float2 hi = *(const float2*)(Qst + (r0+gid+8)*72 + kk*8 + 2*l4);
        qf[kk][0]=__float_as_uint(lo.x); qf[kk][1]=__float_as_uint(hi.x);
        qf[kk][2]=__float_as_uint(lo.y); qf[kk][3]=__float_as_uint(hi.y);
    }
    __syncthreads();   // done reading Qst before K/V overwrite

    #pragma unroll
    for (int i=0;i<4;i++){
        int idx=i*256+tid, row=idx>>4, c4=(idx&15)*4;
        cp16(KS0 + row*72 + c4, Kg + row*64 + c4);
        cp16(VS0 + row*72 + c4, Vg + row*1024 + c4);
    }
    CP_COMMIT;
    #pragma unroll
    for (int i=0;i<4;i++){
        int idx=i*256+tid, row=idx>>4, c4=(idx&15)*4;
        cp16(KS1 + row*72 + c4, Kg + 4096 + row*64 + c4);
        cp16(VS1 + row*72 + c4, Vg + 64 + row*1024 + c4);
    }
    CP_COMMIT;

    float o[8][4];
    #pragma unroll
    for (int n=0;n<8;n++){ o[n][0]=o[n][1]=o[n][2]=o[n][3]=0.f; }
    float m_lo=-1e30f, m_hi=-1e30f, l_lo=0.f, l_hi=0.f;

    for (int kt=0; kt<16; kt++){
        CP_WAIT1;
        __syncthreads();
        const float* Ks_ = (kt&1) ? KS1 : KS0;
        const float* Vs_ = (kt&1) ? VS1 : VS0;

        // ---- S = Q K^T  (16x64 per warp), paired LDS.64 B-frags ----
        float c[8][4];
        #pragma unroll
        for (int j=0;j<8;j++){ c[j][0]=c[j][1]=c[j][2]=c[j][3]=0.f; }
        #pragma unroll
        for (int j=0;j<8;j++){
            #pragma unroll
            for (int kk=0;kk<8;kk++){
                float2 bb = *(const float2*)(Ks_ + (j*8+gid)*72 + kk*8 + 2*l4);
                MMA_TF32(c[j][0],c[j][1],c[j][2],c[j][3],
                         qf[kk][0],qf[kk][1],qf[kk][2],qf[kk][3],
                         __float_as_uint(bb.x),__float_as_uint(bb.y));
            }
        }

        // ---- online softmax (base-2 domain) ----
        float mx_lo=-1e30f, mx_hi=-1e30f;
        #pragma unroll
        for (int j=0;j<8;j++){
            mx_lo = fmaxf(mx_lo, fmaxf(c[j][0], c[j][1]));
            mx_hi = fmaxf(mx_hi, fmaxf(c[j][2], c[j][3]));
        }
        mx_lo = fmaxf(mx_lo, __shfl_xor_sync(0xffffffffu, mx_lo, 1));
        mx_lo = fmaxf(mx_lo, __shfl_xor_sync(0xffffffffu, mx_lo, 2));
        mx_hi = fmaxf(mx_hi, __shfl_xor_sync(0xffffffffu, mx_hi, 1));
        mx_hi = fmaxf(mx_hi, __shfl_xor_sync(0xffffffffu, mx_hi, 2));
        float mn_lo = fmaxf(m_lo, mx_lo), mn_hi = fmaxf(m_hi, mx_hi);
        float al = fex2(m_lo - mn_lo), ah = fex2(m_hi - mn_hi);
        float s_lo=0.f, s_hi=0.f;
        #pragma unroll
        for (int j=0;j<8;j++){
            c[j][0]=fex2(c[j][0]-mn_lo); s_lo+=c[j][0];
            c[j][1]=fex2(c[j][1]-mn_lo); s_lo+=c[j][1];
            c[j][2]=fex2(c[j][2]-mn_hi); s_hi+=c[j][2];
            c[j][3]=fex2(c[j][3]-mn_hi); s_hi+=c[j][3];
        }
        s_lo += __shfl_xor_sync(0xffffffffu, s_lo, 1);
        s_lo += __shfl_xor_sync(0xffffffffu, s_lo, 2);
        s_hi += __shfl_xor_sync(0xffffffffu, s_hi, 1);
        s_hi += __shfl_xor_sync(0xffffffffu, s_hi, 2);
        l_lo = l_lo*al + s_lo;  l_hi = l_hi*ah + s_hi;
        m_lo = mn_lo;           m_hi = mn_hi;
        #pragma unroll
        for (int n=0;n<8;n++){
            o[n][0]*=al; o[n][1]*=al; o[n][2]*=ah; o[n][3]*=ah;
        }

        // ---- O += P V : P A-frags direct from S accum, V^T LDS.64 B-frags --
        #pragma unroll
        for (int t=0;t<8;t++){
            unsigned a0 = tf32u(c[t][0]);
            unsigned a1 = tf32u(c[t][2]);
            unsigned a2 = tf32u(c[t][1]);
            unsigned a3 = tf32u(c[t][3]);
            #pragma unroll
            for (int n=0;n<8;n++){
                float2 bb = *(const float2*)(Vs_ + (n*8+gid)*72 + t*8 + 2*l4);
                MMA_TF32(o[n][0],o[n][1],o[n][2],o[n][3],a0,a1,a2,a3,
                         __float_as_uint(bb.x),__float_as_uint(bb.y));
            }
        }

        __syncthreads();
        if (kt < 14){
            const float* Kp = Kg + (kt+2)*4096;
            const float* Vp = Vg + (kt+2)*64;
            float* kd = (kt&1) ? KS1 : KS0;
            float* vd = (kt&1) ? VS1 : VS0;
            #pragma unroll
            for (int i=0;i<4;i++){
                int idx=i*256+tid, row=idx>>4, c4=(idx&15)*4;
                cp16(kd + row*72 + c4, Kp + row*64 + c4);
                cp16(vd + row*72 + c4, Vp + row*1024 + c4);
            }
        }
        CP_COMMIT;
    }

    float il = 1.f/l_lo, ih = 1.f/l_hi;
    float* Op = g_o + base + qt*8192;
    const int r_lo = r0 + gid, r_hi = r_lo + 8;
    #pragma unroll
    for (int n=0;n<8;n++){
        int col = n*8 + 2*l4;
        *(float2*)(Op + r_lo*64 + col) = make_float2(o[n][0]*il, o[n][1]*il);
        *(float2*)(Op + r_hi*64 + col) = make_float2(o[n][2]*ih, o[n][3]*ih);
    }
}

// ==== Kernel E2: tf32 mma out-proj + residual + LN + transpose ============
// CTA: 128 seq rows x 64 cols, K=256 in 4 chunks of 64.
__global__ __launch_bounds__(256) void kE2(const float* __restrict__ fc,
                                           const float* __restrict__ fcb,
                                           const float* __restrict__ lng,
                                           const float* __restrict__ lnb,
                                           float* __restrict__ out)
{
    extern __shared__ float sme[];
    float* As = sme;           // [128][68] GEMM phase; Cs [128][69] epilogue
    float* Bs = sme + 8832;    // [64][68]
    float* Cs = sme;
    const int stile = blockIdx.x, b = blockIdx.y, tid = threadIdx.x;
    const int w=tid>>5, lane=tid&31, gid=lane>>2, l4=lane&3;
    const int r0 = w*16;
    const int s0 = stile*128;

    float c[8][4];
    #pragma unroll
    for (int j=0;j<8;j++){ c[j][0]=c[j][1]=c[j][2]=c[j][3]=0.f; }

    for (int h=0; h<4; h++){
        __syncthreads();
        const float* Ap = g_o + ((b*4+h)<<16) + s0*64;
        #pragma unroll
        for (int i=0;i<8;i++){
            int idx=i*256+tid, row=idx>>4, c4=(idx&15)*4;
            *(float4*)(As + row*68 + c4) = *(const float4*)(Ap + row*64 + c4);
        }
        #pragma unroll
        for (int i=0;i<4;i++){
            int idx=i*256+tid, row=idx>>4, c4=(idx&15)*4;
            *(float4*)(Bs + row*68 + c4) = *(const float4*)(fc + (h*64+row)*64 + c4);
        }
        __syncthreads();
        unsigned af[8][4];
        #pragma unroll
        for (int kk=0;kk<8;kk++){
            af[kk][0]=__float_as_uint(As[(r0+gid  )*68 + kk*8   + l4]);
            af[kk][1]=__float_as_uint(As[(r0+gid+8)*68 + kk*8   + l4]);
            af[kk][2]=__float_as_uint(As[(r0+gid  )*68 + kk*8+4 + l4]);
            af[kk][3]=__float_as_uint(As[(r0+gid+8)*68 + kk*8+4 + l4]);
        }
        #pragma unroll
        for (int j=0;j<8;j++){
            #pragma unroll
            for (int kk=0;kk<8;kk++){
                unsigned b0=__float_as_uint(Bs[(kk*8+l4  )*68 + j*8+gid]);
                unsigned b1=__float_as_uint(Bs[(kk*8+l4+4)*68 + j*8+gid]);
                MMA_TF32(c[j][0],c[j][1],c[j][2],c[j][3],
                         af[kk][0],af[kk][1],af[kk][2],af[kk][3],b0,b1);
            }
        }
    }
    __syncthreads();
    // epilogue: bias + residual into Cs (stride 69)
    const int r_lo = r0 + gid, r_hi = r_lo + 8;
    #pragma unroll
    for (int j=0;j<8;j++){
        int col = j*8 + 2*l4;
        float b0 = fcb[col], b1 = fcb[col+1];
        Cs[r_lo*69+col  ] = c[j][0] + b0 + g_cf[b*65536 + (s0+r_lo)*64 + col  ];
        Cs[r_lo*69+col+1] = c[j][1] + b1 + g_cf[b*65536 + (s0+r_lo)*64 + col+1];
        Cs[r_hi*69+col  ] = c[j][2] + b0 + g_cf[b*65536 + (s0+r_hi)*64 + col  ];
        Cs[r_hi*69+col+1] = c[j][3] + b1 + g_cf[b*65536 + (s0+r_hi)*64 + col+1];
    }
    __syncthreads();
    // LN per row: warp w handles rows w*16..w*16+15
    for (int rr=0; rr<16; rr++){
        int r = w*16 + rr;
        float v0 = Cs[r*69+lane], v1 = Cs[r*69+lane+32];
        float sm = v0+v1, sq = v0*v0 + v1*v1;
        #pragma unroll
        for (int off=16; off; off>>=1){
            sm += __shfl_xor_sync(0xffffffffu, sm, off);
            sq += __shfl_xor_sync(0xffffffffu, sq, off);
        }
        float mu = sm*(1.f/64.f);
        float var = sq*(1.f/64.f) - mu*mu;
        float rstd = rsqrtf(var + 1e-6f);
        Cs[r*69+lane]    = (v0-mu)*rstd*lng[lane]    + lnb[lane];
        Cs[r*69+lane+32] = (v1-mu)*rstd*lng[lane+32] + lnb[lane+32];
    }
    __syncthreads();
    // transposed store: out[b][c][s]
    #pragma unroll
    for (int i=0;i<32;i++){
        int idx = i*256 + tid;
        int cc = idx>>7, sl = idx&127;
        out[(((b<<6)+cc)<<10) + s0 + sl] = Cs[sl*69+cc];
    }
}

// ============================== launcher ===================================
extern "C" void kernel_launch(void* const* d_in, const int* in_sizes, int n_in,
                              void* d_out, int out_size)
{
    const float* x      = (const float*)d_in[0];
    const float* memory = (const float*)d_in[1];
    const float* wb_w   = (const float*)d_in[2];
    const float* wb_b   = (const float*)d_in[3];
    const float* a1_wq  = (const float*)d_in[4];
    const float* a1_bq  = (const float*)d_in[5];
    const float* a1_wk  = (const float*)d_in[6];
    const float* a1_bk  = (const float*)d_in[7];
    const float* a1_wv  = (const float*)d_in[8];
    const float* a1_bv  = (const float*)d_in[9];
    const float* a1_fc  = (const float*)d_in[10];
    const float* a1_fcb = (const float*)d_in[11];
    const float* a1_lng = (const float*)d_in[12];
    const float* a1_lnb = (const float*)d_in[13];
    const float* a2_wq  = (const float*)d_in[14];
    const float* a2_bq  = (const float*)d_in[15];
    const float* a2_wk  = (const float*)d_in[16];
    const float* a2_bk  = (const float*)d_in[17];
    const float* a2_wv  = (const float*)d_in[18];
    const float* a2_bv  = (const float*)d_in[19];
    const float* a2_fc  = (const float*)d_in[20];
    const float* a2_fcb = (const float*)d_in[21];
    const float* a2_lng = (const float*)d_in[22];
    const float* a2_lnb = (const float*)d_in[23];
    float* out = (float*)d_out;

    float *pq=0, *pk=0, *pv=0;
    cudaGetSymbolAddress((void**)&pq, g_q);
    cudaGetSymbolAddress((void**)&pk, g_k);
    cudaGetSymbolAddress((void**)&pv, g_v);

    const int kcm_smem = 17536*4;          // 70144 B
    const int kd_smem  = 18432*4;          // 73728 B -> 2 CTAs/SM
    const int ke_smem  = (8832+4352)*4;    // 52736 B
    cudaFuncSetAttribute(kCm, cudaFuncAttributeMaxDynamicSharedMemorySize, kcm_smem);
    cudaFuncSetAttribute(kD,  cudaFuncAttributeMaxDynamicSharedMemorySize, kd_smem);
    cudaFuncSetAttribute(kE2, cudaFuncAttributeMaxDynamicSharedMemorySize, ke_smem);

    kA<<<NB, 1024>>>(x, wb_w, wb_b);
    dim3 gP(16, NB);
    kP<<<gP, 256>>>(x);
    kB<<<NB, 512>>>(memory, a1_wq, a1_bq, a1_wk, a1_bk, a1_wv, a1_bv,
                    a1_fc, a1_fcb, a1_lng, a1_lnb);
    dim3 gC(128, 2, 3);
    kCm<<<gC, 256, kcm_smem>>>(a2_wq, a2_wk, a2_wv, a2_bq, a2_bk, a2_bv, pq, pk, pv);
    dim3 gD(8, 4, NB);
    kD<<<gD, 256, kd_smem>>>();
    dim3 gE(8, NB);
    kE2<<<gE, 256, ke_smem>>>(a2_fc, a2_fcb, a2_lng, a2_lnb, out);
}

// round 9
// speedup vs baseline: 1.5031x; 1.5031x over previous
#include <cuda_runtime.h>
#include <math.h>

#define NB   16
#define SEQ  1024
#define CH   64
#define NC   5
#define MD   96

// ---------------- scratch (device globals; no allocation) ----------------
__device__ float g_w1[NB*SEQ*NC];
__device__ float g_w2[NB*NC*SEQ];
__device__ float g_cf[NB*SEQ*CH];
__device__ float g_pool[NB*16*NC*64];   // pooling partials [b][st][n*64+c]
__device__ float g_q [NB*4*SEQ*64];   // [b][h][s][d']  (d pair-interleaved)
__device__ float g_k [NB*4*SEQ*64];   // [b][h][s][d']  (d pair-interleaved)
__device__ float g_v [NB*4*SEQ*64];   // [b][h][d][s]   (TRANSPOSED)
__device__ float g_o [NB*4*SEQ*64];

// ---------------- helpers ----------------
__device__ __forceinline__ float tf32r(float x){
    unsigned u; asm("cvt.rna.tf32.f32 %0, %1;" : "=r"(u) : "f"(x));
    return __uint_as_float(u);
}
__device__ __forceinline__ unsigned tf32u(float x){
    unsigned u; asm("cvt.rna.tf32.f32 %0, %1;" : "=r"(u) : "f"(x));
    return u;
}
__device__ __forceinline__ float fex2(float x){
    float r; asm("ex2.approx.ftz.f32 %0, %1;" : "=f"(r) : "f"(x));
    return r;
}
__device__ __forceinline__ void cp16(void* dst, const void* src){
    unsigned d = (unsigned)__cvta_generic_to_shared(dst);
    asm volatile("cp.async.cg.shared.global [%0], [%1], 16;" :: "r"(d), "l"(src));
}
#define CP_COMMIT asm volatile("cp.async.commit_group;")
#define CP_WAIT1  asm volatile("cp.async.wait_group 1;")

#define MMA_TF32(c0,c1,c2,c3,a0,a1,a2,a3,b0,b1)                               \
  asm volatile("mma.sync.aligned.m16n8k8.row.col.f32.tf32.tf32.f32 "          \
    "{%0,%1,%2,%3}, {%4,%5,%6,%7}, {%8,%9}, {%0,%1,%2,%3};"                   \
    : "+f"(c0),"+f"(c1),"+f"(c2),"+f"(c3)                                     \
    : "r"(a0),"r"(a1),"r"(a2),"r"(a3),"r"(b0),"r"(b1))

// ================= Kernel A: weight = xt@wb_w, both softmaxes =============
__global__ __launch_bounds__(1024) void kA(const float* __restrict__ x,
                                           const float* __restrict__ wbw,
                                           const float* __restrict__ wbb)
{
    const int b = blockIdx.x, s = threadIdx.x;
    __shared__ float ws[CH*NC];
    __shared__ float red[32*NC];
    __shared__ float Mx[NC], Sx[NC];
    if (s < CH*NC) ws[s] = wbw[s];
    __syncthreads();

    const float* xb = x + b*(CH*SEQ) + s;
    float w[NC];
    #pragma unroll
    for (int n=0;n<NC;n++) w[n] = wbb[n];
    #pragma unroll 8
    for (int c=0;c<CH;c++){
        float xv = xb[c<<10];
        #pragma unroll
        for (int n=0;n<NC;n++) w[n] = fmaf(xv, ws[c*NC+n], w[n]);
    }

    {
        float mx = w[0];
        #pragma unroll
        for (int n=1;n<NC;n++) mx = fmaxf(mx, w[n]);
        float e[NC], ssum = 0.f;
        #pragma unroll
        for (int n=0;n<NC;n++){ e[n] = __expf(w[n]-mx); ssum += e[n]; }
        float inv = 1.f/ssum;
        float* w1p = g_w1 + b*(SEQ*NC) + s*NC;
        #pragma unroll
        for (int n=0;n<NC;n++) w1p[n] = e[n]*inv;
    }

    const int lane = s & 31, wid = s >> 5;
    float r5[NC];
    #pragma unroll
    for (int n=0;n<NC;n++) r5[n] = w[n];
    #pragma unroll
    for (int off=16; off; off>>=1)
        #pragma unroll
        for (int n=0;n<NC;n++) r5[n] = fmaxf(r5[n], __shfl_xor_sync(0xffffffffu, r5[n], off));
    if (lane==0){
        #pragma unroll
        for (int n=0;n<NC;n++) red[wid*NC+n] = r5[n];
    }
    __syncthreads();
    if (wid==0){
        #pragma unroll
        for (int n=0;n<NC;n++) r5[n] = red[lane*NC+n];
        #pragma unroll
        for (int off=16; off; off>>=1)
            #pragma unroll
            for (int n=0;n<NC;n++) r5[n] = fmaxf(r5[n], __shfl_xor_sync(0xffffffffu, r5[n], off));
        if (lane==0){
            #pragma unroll
            for (int n=0;n<NC;n++) Mx[n] = r5[n];
        }
    }
    __syncthreads();
    float e2[NC];
    #pragma unroll
    for (int n=0;n<NC;n++){ e2[n] = __expf(w[n]-Mx[n]); r5[n] = e2[n]; }
    #pragma unroll
    for (int off=16; off; off>>=1)
        #pragma unroll
        for (int n=0;n<NC;n++) r5[n] += __shfl_xor_sync(0xffffffffu, r5[n], off);
    if (lane==0){
        #pragma unroll
        for (int n=0;n<NC;n++) red[wid*NC+n] = r5[n];
    }
    __syncthreads();
    if (wid==0){
        #pragma unroll
        for (int n=0;n<NC;n++) r5[n] = red[lane*NC+n];
        #pragma unroll
        for (int off=16; off; off>>=1)
            #pragma unroll
            for (int n=0;n<NC;n++) r5[n] += __shfl_xor_sync(0xffffffffu, r5[n], off);
        if (lane==0){
            #pragma unroll
            for (int n=0;n<NC;n++) Sx[n] = r5[n];
        }
    }
    __syncthreads();
    float* w2p = g_w2 + b*(NC*SEQ) + s;
    #pragma unroll
    for (int n=0;n<NC;n++) w2p[n<<10] = e2[n] / Sx[n];
}

// ====== Kernel P: parallel class pooling partials =========================
__global__ __launch_bounds__(256) void kP(const float* __restrict__ x)
{
    const int st = blockIdx.x, b = blockIdx.y, tid = threadIdx.x;
    __shared__ float xs[64*65];
    __shared__ float w2s[NC*64];
    const int s0 = st*64;
    #pragma unroll
    for (int i=0;i<16;i++){
        int idx = i*256 + tid;
        int c = idx>>6, sl = idx&63;
        xs[c*65+sl] = x[b*65536 + (c<<10) + s0 + sl];
    }
    for (int idx=tid; idx<NC*64; idx+=256)
        w2s[idx] = g_w2[b*5120 + ((idx>>6)<<10) + s0 + (idx&63)];
    __syncthreads();
    for (int idx=tid; idx<NC*64; idx+=256){
        const int n = idx>>6, c = idx&63;
        float a = 0.f;
        #pragma unroll 8
        for (int sl=0; sl<64; sl++) a = fmaf(w2s[n*64+sl], xs[c*65+sl], a);
        g_pool[(b*16+st)*320 + idx] = a;
    }
}

// ====== Kernel B: reduce pooling, MHA1 (5 tokens vs memory), redistribute ==
__global__ __launch_bounds__(512) void kB(
    const float* __restrict__ memory,
    const float* __restrict__ wq, const float* __restrict__ bq,
    const float* __restrict__ wk, const float* __restrict__ bk,
    const float* __restrict__ wv, const float* __restrict__ bv,
    const float* __restrict__ fc, const float* __restrict__ fcb,
    const float* __restrict__ lng, const float* __restrict__ lnb)
{
    const int b = blockIdx.x, tid = threadIdx.x;
    __shared__ float cf1s[NC*64];
    __shared__ float mems[NC*MD];
    __shared__ float qh[NC*MD], kh[NC*MD], vh[NC*64];
    __shared__ float Ssm[NC*NC];
    __shared__ float osm[NC*64];
    __shared__ float projs[NC*64];

    if (tid < 320){
        float acc = 0.f;
        #pragma unroll
        for (int st=0; st<16; st++) acc += g_pool[(b*16+st)*320 + tid];
        cf1s[tid] = acc;
    }
    if (tid < NC*MD) mems[tid] = memory[tid];
    __syncthreads();

    if (tid < 480){
        const int n = tid/96, j = tid - n*96;
        float q = bq[j];
        #pragma unroll
        for (int d=0; d<64; d++) q = fmaf(cf1s[n*64+d], wq[d*96+j], q);
        qh[tid] = q * 0.102062072615966f;
        float kk = bk[j];
        #pragma unroll
        for (int d=0; d<96; d++) kk = fmaf(mems[n*96+d], wk[d*96+j], kk);
        kh[tid] = kk;
    }
    if (tid < 320){
        const int n = tid>>6, c = tid&63;
        float vv = bv[c];
        #pragma unroll
        for (int d=0; d<96; d++) vv = fmaf(mems[n*96+d], wv[d*64+c], vv);
        vh[tid] = vv;
    }
    __syncthreads();

    if (tid < 25){
        const int i = tid/5, j = tid - (tid/5)*5;
        float sv = 0.f;
        #pragma unroll
        for (int d=0; d<96; d++) sv = fmaf(qh[i*96+d], kh[j*96+d], sv);
        Ssm[tid] = sv;
    }
    __syncthreads();
    if (tid < 5){
        float m = Ssm[tid*5];
        #pragma unroll
        for (int j=1;j<5;j++) m = fmaxf(m, Ssm[tid*5+j]);
        float p[5], sum = 0.f;
        #pragma unroll
        for (int j=0;j<5;j++){ p[j] = __expf(Ssm[tid*5+j]-m); sum += p[j]; }
        float inv = 1.f/sum;
        #pragma unroll
        for (int j=0;j<5;j++) Ssm[tid*5+j] = p[j]*inv;
    }
    __syncthreads();
    if (tid < 320){
        const int n = tid>>6, c = tid&63;
        float o = 0.f;
        #pragma unroll
        for (int j=0;j<5;j++) o = fmaf(Ssm[n*5+j], vh[j*64+c], o);
        osm[tid] = o;
    }
    __syncthreads();
    if (tid < 320){
        const int n = tid>>6, c = tid&63;
        float p = fcb[c] + cf1s[tid];
        #pragma unroll
        for (int k=0;k<64;k++) p = fmaf(osm[n*64+k], fc[k*64+c], p);
        projs[tid] = p;
    }
    __syncthreads();
    if (tid < 160){
        const int n = tid>>5, lane = tid&31;
        float v0 = projs[n*64+lane], v1 = projs[n*64+lane+32];
        float sm = v0+v1, sq = v0*v0 + v1*v1;
        #pragma unroll
        for (int off=16; off; off>>=1){
            sm += __shfl_xor_sync(0xffffffffu, sm, off);
            sq += __shfl_xor_sync(0xffffffffu, sq, off);
        }
        float mu = sm*(1.f/64.f);
        float var = sq*(1.f/64.f) - mu*mu;
        float rs = rsqrtf(var + 1e-6f);
        cf1s[n*64+lane]    = (v0-mu)*rs*lng[lane]    + lnb[lane];
        cf1s[n*64+lane+32] = (v1-mu)*rs*lng[lane+32] + lnb[lane+32];
    }
    __syncthreads();
    for (int it=0; it<128; it++){
        int idx = it*512 + tid;
        int s = idx>>6, c = idx&63;
        const float* w1p = g_w1 + b*5120 + s*5;
        float a = 0.f;
        #pragma unroll
        for (int n=0;n<5;n++) a = fmaf(w1p[n], cf1s[n*64+c], a);
        g_cf[b*65536 + idx] = a;
    }
}

// ====== Kernel Cm: fused QKV projection via tf32 mma, z fused in-CTA ======
// A tile + A-fragments loaded ONCE, reused for Q, K, V weight tiles.
// z<2 (Q,K): store with d pair-interleaved; z==2 (V): store transposed [d][s].
__global__ __launch_bounds__(256) void kCm(
    const float* __restrict__ wq, const float* __restrict__ wk, const float* __restrict__ wv,
    const float* __restrict__ bq, const float* __restrict__ bk, const float* __restrict__ bv,
    float* __restrict__ pq, float* __restrict__ pk, float* __restrict__ pv)
{
    extern __shared__ float smc[];
    float* Ast = smc;          // [128][68]
    float* Ws  = smc + 8704;   // [64][136]
    float* bs  = smc + 17408;  // [128]
    const int mt=blockIdx.x, nt=blockIdx.y;
    const int tid=threadIdx.x, w=tid>>5, lane=tid&31, gid=lane>>2, l4=lane&3;

    const float* Ap = g_cf + mt*128*64;
    #pragma unroll
    for (int i=0;i<8;i++){
        int idx=i*256+tid, row=idx>>4, c4=(idx&15)*4;
        *(float4*)(Ast + row*68 + c4) = *(const float4*)(Ap + row*64 + c4);
    }
    __syncthreads();

    unsigned af[8][4];
    const int r0 = w*16;
    #pragma unroll
    for (int kk=0;kk<8;kk++){
        af[kk][0]=__float_as_uint(Ast[(r0+gid  )*68 + kk*8   + l4]);
        af[kk][1]=__float_as_uint(Ast[(r0+gid+8)*68 + kk*8   + l4]);
        af[kk][2]=__float_as_uint(Ast[(r0+gid  )*68 + kk*8+4 + l4]);
        af[kk][3]=__float_as_uint(Ast[(r0+gid+8)*68 + kk*8+4 + l4]);
    }

    const int row_lo = mt*128 + r0 + gid;
    const int bidx = row_lo>>10, s_lo = row_lo&1023;

    #pragma unroll
    for (int z=0; z<3; z++){
        const float* W  = (z==0)?wq:((z==1)?wk:wv);
        const float* Bp = (z==0)?bq:((z==1)?bk:bv);
        float*       O  = (z==0)?pq:((z==1)?pk:pv);

        __syncthreads();   // prior z's readers done with Ws
        #pragma unroll
        for (int i=0;i<8;i++){
            int idx=i*256+tid, row=idx>>5, c4=(idx&31)*4;
            *(float4*)(Ws + row*136 + c4) = *(const float4*)(W + row*256 + nt*128 + c4);
        }
        if (tid<128) bs[tid] = Bp[nt*128+tid];
        __syncthreads();

        float c[16][4];
        #pragma unroll
        for (int j=0;j<16;j++){ c[j][0]=c[j][1]=c[j][2]=c[j][3]=0.f; }
        #pragma unroll
        for (int j=0;j<16;j++){
            #pragma unroll
            for (int kk=0;kk<8;kk++){
                unsigned b0=__float_as_uint(Ws[(kk*8+l4  )*136 + j*8+gid]);
                unsigned b1=__float_as_uint(Ws[(kk*8+l4+4)*136 + j*8+gid]);
                MMA_TF32(c[j][0],c[j][1],c[j][2],c[j][3],
                         af[kk][0],af[kk][1],af[kk][2],af[kk][3],b0,b1);
            }
        }
        #pragma unroll
        for (int j=0;j<16;j++){
            int cl = j*8 + 2*l4;
            int col0 = nt*128 + cl;
            int h = col0>>6, d0 = col0&63, d1 = d0+1;
            float* op = O + (((bidx<<2)+h)<<16);
            float v00 = tf32r(c[j][0]+bs[cl]);
            float v01 = tf32r(c[j][1]+bs[cl+1]);
            float v10 = tf32r(c[j][2]+bs[cl]);
            float v11 = tf32r(c[j][3]+bs[cl+1]);
            if (z < 2){
                int dp0 = (d0&56)|((d0&3)<<1)|((d0&4)>>2);
                int dp1 = (d1&56)|((d1&3)<<1)|((d1&4)>>2);
                op[ s_lo   *64 + dp0] = v00;
                op[ s_lo   *64 + dp1] = v01;
                op[(s_lo+8)*64 + dp0] = v10;
                op[(s_lo+8)*64 + dp1] = v11;
            } else {
                op[d0*1024 + s_lo  ] = v00;
                op[d1*1024 + s_lo  ] = v01;
                op[d0*1024 + s_lo+8] = v10;
                op[d1*1024 + s_lo+8] = v11;
            }
        }
    }
}

// ========== Kernel D: tf32 mma flash attention (2 CTAs/SM) ================
__global__ __launch_bounds__(256, 2) void kD()
{
    extern __shared__ float sm[];
    float* KS0 = sm;             // [64][72]
    float* VS0 = sm + 4608;      // [64][72]  (V^T tile: [d][s])
    float* KS1 = sm + 9216;      // [64][72]
    float* VS1 = sm + 13824;     // [64][72]
    float* Qst = sm;             // alias [128][72] (used before K/V loads)

    const int qt=blockIdx.x, h=blockIdx.y, b=blockIdx.z;
    const int tid=threadIdx.x, w=tid>>5, lane=tid&31;
    const int gid=lane>>2, l4=lane&3;
    const int base=((b*4+h)<<16);

    const float* Kg = g_k + base;
    const float* Vg = g_v + base;          // [64 d][1024 s]
    const float* Qg = g_q + base + qt*8192;

    // stage Q scaled by log2(e)/sqrt(64) so softmax uses bare ex2
    const float QSC = 0.125f * 1.4426950408889634f;
    #pragma unroll
    for (int i=0;i<8;i++){
        int idx=i*256+tid, row=idx>>4, c4=(idx&15)*4;
        float4 v = *(const float4*)(Qg + row*64 + c4);
        Qst[row*72+c4+0]=v.x*QSC; Qst[row*72+c4+1]=v.y*QSC;
        Qst[row*72+c4+2]=v.z*QSC; Qst[row*72+c4+3]=v.w*QSC;
    }
    __syncthreads();
    unsigned qf[8][4];
    const int r0 = w*16;
    #pragma unroll
    for (int kk=0;kk<8;kk++){
        float2 lo = *(const float2*)(Qst + (r0+gid  )*72 + kk*8 + 2*l4);
        float2 hi = *(const float2*)(Qst + (r0+gid+8)*72 + kk*8 + 2*l4);
        qf[kk][0]=__float_as_uint(lo.x); qf[kk][1]=__float_as_uint(hi.x);
        qf[kk][2]=__float_as_uint(lo.y); qf[kk][3]=__float_as_uint(hi.y);
    }
    __syncthreads();   // done reading Qst before K/V overwrite

    #pragma unroll
    for (int i=0;i<4;i++){
        int idx=i*256+tid, row=idx>>4, c4=(idx&15)*4;
        cp16(KS0 + row*72 + c4, Kg + row*64 + c4);
        cp16(VS0 + row*72 + c4, Vg + row*1024 + c4);
    }
    CP_COMMIT;
    #pragma unroll
    for (int i=0;i<4;i++){
        int idx=i*256+tid, row=idx>>4, c4=(idx&15)*4;
        cp16(KS1 + row*72 + c4, Kg + 4096 + row*64 + c4);
        cp16(VS1 + row*72 + c4, Vg + 64 + row*1024 + c4);
    }
    CP_COMMIT;

    float o[8][4];
    #pragma unroll
    for (int n=0;n<8;n++){ o[n][0]=o[n][1]=o[n][2]=o[n][3]=0.f; }
    float m_lo=-1e30f, m_hi=-1e30f, l_lo=0.f, l_hi=0.f;

    for (int kt=0; kt<16; kt++){
        CP_WAIT1;
        __syncthreads();
        const float* Ks_ = (kt&1) ? KS1 : KS0;
        const float* Vs_ = (kt&1) ? VS1 : VS0;

        // ---- S = Q K^T  (16x64 per warp), paired LDS.64 B-frags ----
        float c[8][4];
        #pragma unroll
        for (int j=0;j<8;j++){ c[j][0]=c[j][1]=c[j][2]=c[j][3]=0.f; }
        #pragma unroll
        for (int j=0;j<8;j++){
            #pragma unroll
            for (int kk=0;kk<8;kk++){
                float2 bb = *(const float2*)(Ks_ + (j*8+gid)*72 + kk*8 + 2*l4);
                MMA_TF32(c[j][0],c[j][1],c[j][2],c[j][3],
                         qf[kk][0],qf[kk][1],qf[kk][2],qf[kk][3],
                         __float_as_uint(bb.x),__float_as_uint(bb.y));
            }
        }

        // ---- online softmax (base-2 domain) ----
        float mx_lo=-1e30f, mx_hi=-1e30f;
        #pragma unroll
        for (int j=0;j<8;j++){
            mx_lo = fmaxf(mx_lo, fmaxf(c[j][0], c[j][1]));
            mx_hi = fmaxf(mx_hi, fmaxf(c[j][2], c[j][3]));
        }
        mx_lo = fmaxf(mx_lo, __shfl_xor_sync(0xffffffffu, mx_lo, 1));
        mx_lo = fmaxf(mx_lo, __shfl_xor_sync(0xffffffffu, mx_lo, 2));
        mx_hi = fmaxf(mx_hi, __shfl_xor_sync(0xffffffffu, mx_hi, 1));
        mx_hi = fmaxf(mx_hi, __shfl_xor_sync(0xffffffffu, mx_hi, 2));
        float mn_lo = fmaxf(m_lo, mx_lo), mn_hi = fmaxf(m_hi, mx_hi);
        float al = fex2(m_lo - mn_lo), ah = fex2(m_hi - mn_hi);
        float s_lo=0.f, s_hi=0.f;
        #pragma unroll
        for (int j=0;j<8;j++){
            c[j][0]=fex2(c[j][0]-mn_lo); s_lo+=c[j][0];
            c[j][1]=fex2(c[j][1]-mn_lo); s_lo+=c[j][1];
            c[j][2]=fex2(c[j][2]-mn_hi); s_hi+=c[j][2];
            c[j][3]=fex2(c[j][3]-mn_hi); s_hi+=c[j][3];
        }
        s_lo += __shfl_xor_sync(0xffffffffu, s_lo, 1);
        s_lo += __shfl_xor_sync(0xffffffffu, s_lo, 2);
        s_hi += __shfl_xor_sync(0xffffffffu, s_hi, 1);
        s_hi += __shfl_xor_sync(0xffffffffu, s_hi, 2);
        l_lo = l_lo*al + s_lo;  l_hi = l_hi*ah + s_hi;
        m_lo = mn_lo;           m_hi = mn_hi;
        #pragma unroll
        for (int n=0;n<8;n++){
            o[n][0]*=al; o[n][1]*=al; o[n][2]*=ah; o[n][3]*=ah;
        }

        // ---- O += P V : P A-frags direct from S accum, V^T LDS.64 B-frags --
        #pragma unroll
        for (int t=0;t<8;t++){
            unsigned a0 = tf32u(c[t][0]);
            unsigned a1 = tf32u(c[t][2]);
            unsigned a2 = tf32u(c[t][1]);
            unsigned a3 = tf32u(c[t][3]);
            #pragma unroll
            for (int n=0;n<8;n++){
                float2 bb = *(const float2*)(Vs_ + (n*8+gid)*72 + t*8 + 2*l4);
                MMA_TF32(o[n][0],o[n][1],o[n][2],o[n][3],a0,a1,a2,a3,
                         __float_as_uint(bb.x),__float_as_uint(bb.y));
            }
        }

        __syncthreads();
        if (kt < 14){
            const float* Kp = Kg + (kt+2)*4096;
            const float* Vp = Vg + (kt+2)*64;
            float* kd = (kt&1) ? KS1 : KS0;
            float* vd = (kt&1) ? VS1 : VS0;
            #pragma unroll
            for (int i=0;i<4;i++){
                int idx=i*256+tid, row=idx>>4, c4=(idx&15)*4;
                cp16(kd + row*72 + c4, Kp + row*64 + c4);
                cp16(vd + row*72 + c4, Vp + row*1024 + c4);
            }
        }
        CP_COMMIT;
    }

    float il = 1.f/l_lo, ih = 1.f/l_hi;
    float* Op = g_o + base + qt*8192;
    const int r_lo = r0 + gid, r_hi = r_lo + 8;
    #pragma unroll
    for (int n=0;n<8;n++){
        int col = n*8 + 2*l4;
        *(float2*)(Op + r_lo*64 + col) = make_float2(o[n][0]*il, o[n][1]*il);
        *(float2*)(Op + r_hi*64 + col) = make_float2(o[n][2]*ih, o[n][3]*ih);
    }
}

// ==== Kernel E2: tf32 mma out-proj + residual + LN + transpose ============
__global__ __launch_bounds__(256) void kE2(const float* __restrict__ fc,
                                           const float* __restrict__ fcb,
                                           const float* __restrict__ lng,
                                           const float* __restrict__ lnb,
                                           float* __restrict__ out)
{
    extern __shared__ float sme[];
    float* As = sme;           // [128][68] GEMM phase; Cs [128][69] epilogue
    float* Bs = sme + 8832;    // [64][68]
    float* Cs = sme;
    const int stile = blockIdx.x, b = blockIdx.y, tid = threadIdx.x;
    const int w=tid>>5, lane=tid&31, gid=lane>>2, l4=lane&3;
    const int r0 = w*16;
    const int s0 = stile*128;

    float c[8][4];
    #pragma unroll
    for (int j=0;j<8;j++){ c[j][0]=c[j][1]=c[j][2]=c[j][3]=0.f; }

    for (int h=0; h<4; h++){
        __syncthreads();
        const float* Ap = g_o + ((b*4+h)<<16) + s0*64;
        #pragma unroll
        for (int i=0;i<8;i++){
            int idx=i*256+tid, row=idx>>4, c4=(idx&15)*4;
            *(float4*)(As + row*68 + c4) = *(const float4*)(Ap + row*64 + c4);
        }
        #pragma unroll
        for (int i=0;i<4;i++){
            int idx=i*256+tid, row=idx>>4, c4=(idx&15)*4;
            *(float4*)(Bs + row*68 + c4) = *(const float4*)(fc + (h*64+row)*64 + c4);
        }
        __syncthreads();
        unsigned af[8][4];
        #pragma unroll
        for (int kk=0;kk<8;kk++){
            af[kk][0]=__float_as_uint(As[(r0+gid  )*68 + kk*8   + l4]);
            af[kk][1]=__float_as_uint(As[(r0+gid+8)*68 + kk*8   + l4]);
            af[kk][2]=__float_as_uint(As[(r0+gid  )*68 + kk*8+4 + l4]);
            af[kk][3]=__float_as_uint(As[(r0+gid+8)*68 + kk*8+4 + l4]);
        }
        #pragma unroll
        for (int j=0;j<8;j++){
            #pragma unroll
            for (int kk=0;kk<8;kk++){
                unsigned b0=__float_as_uint(Bs[(kk*8+l4  )*68 + j*8+gid]);
                unsigned b1=__float_as_uint(Bs[(kk*8+l4+4)*68 + j*8+gid]);
                MMA_TF32(c[j][0],c[j][1],c[j][2],c[j][3],
                         af[kk][0],af[kk][1],af[kk][2],af[kk][3],b0,b1);
            }
        }
    }
    __syncthreads();
    const int r_lo = r0 + gid, r_hi = r_lo + 8;
    #pragma unroll
    for (int j=0;j<8;j++){
        int col = j*8 + 2*l4;
        float b0 = fcb[col], b1 = fcb[col+1];
        Cs[r_lo*69+col  ] = c[j][0] + b0 + g_cf[b*65536 + (s0+r_lo)*64 + col  ];
        Cs[r_lo*69+col+1] = c[j][1] + b1 + g_cf[b*65536 + (s0+r_lo)*64 + col+1];
        Cs[r_hi*69+col  ] = c[j][2] + b0 + g_cf[b*65536 + (s0+r_hi)*64 + col  ];
        Cs[r_hi*69+col+1] = c[j][3] + b1 + g_cf[b*65536 + (s0+r_hi)*64 + col+1];
    }
    __syncthreads();
    for (int rr=0; rr<16; rr++){
        int r = w*16 + rr;
        float v0 = Cs[r*69+lane], v1 = Cs[r*69+lane+32];
        float sm = v0+v1, sq = v0*v0 + v1*v1;
        #pragma unroll
        for (int off=16; off; off>>=1){
            sm += __shfl_xor_sync(0xffffffffu, sm, off);
            sq += __shfl_xor_sync(0xffffffffu, sq, off);
        }
        float mu = sm*(1.f/64.f);
        float var = sq*(1.f/64.f) - mu*mu;
        float rstd = rsqrtf(var + 1e-6f);
        Cs[r*69+lane]    = (v0-mu)*rstd*lng[lane]    + lnb[lane];
        Cs[r*69+lane+32] = (v1-mu)*rstd*lng[lane+32] + lnb[lane+32];
    }
    __syncthreads();
    #pragma unroll
    for (int i=0;i<32;i++){
        int idx = i*256 + tid;
        int cc = idx>>7, sl = idx&127;
        out[(((b<<6)+cc)<<10) + s0 + sl] = Cs[sl*69+cc];
    }
}

// ============================== launcher ===================================
extern "C" void kernel_launch(void* const* d_in, const int* in_sizes, int n_in,
                              void* d_out, int out_size)
{
    const float* x      = (const float*)d_in[0];
    const float* memory = (const float*)d_in[1];
    const float* wb_w   = (const float*)d_in[2];
    const float* wb_b   = (const float*)d_in[3];
    const float* a1_wq  = (const float*)d_in[4];
    const float* a1_bq  = (const float*)d_in[5];
    const float* a1_wk  = (const float*)d_in[6];
    const float* a1_bk  = (const float*)d_in[7];
    const float* a1_wv  = (const float*)d_in[8];
    const float* a1_bv  = (const float*)d_in[9];
    const float* a1_fc  = (const float*)d_in[10];
    const float* a1_fcb = (const float*)d_in[11];
    const float* a1_lng = (const float*)d_in[12];
    const float* a1_lnb = (const float*)d_in[13];
    const float* a2_wq  = (const float*)d_in[14];
    const float* a2_bq  = (const float*)d_in[15];
    const float* a2_wk  = (const float*)d_in[16];
    const float* a2_bk  = (const float*)d_in[17];
    const float* a2_wv  = (const float*)d_in[18];
    const float* a2_bv  = (const float*)d_in[19];
    const float* a2_fc  = (const float*)d_in[20];
    const float* a2_fcb = (const float*)d_in[21];
    const float* a2_lng = (const float*)d_in[22];
    const float* a2_lnb = (const float*)d_in[23];
    float* out = (float*)d_out;

    float *pq=0, *pk=0, *pv=0;
    cudaGetSymbolAddress((void**)&pq, g_q);
    cudaGetSymbolAddress((void**)&pk, g_k);
    cudaGetSymbolAddress((void**)&pv, g_v);

    const int kcm_smem = 17536*4;          // 70144 B
    const int kd_smem  = 18432*4;          // 73728 B -> 2 CTAs/SM
    const int ke_smem  = (8832+4352)*4;    // 52736 B
    cudaFuncSetAttribute(kCm, cudaFuncAttributeMaxDynamicSharedMemorySize, kcm_smem);
    cudaFuncSetAttribute(kD,  cudaFuncAttributeMaxDynamicSharedMemorySize, kd_smem);
    cudaFuncSetAttribute(kE2, cudaFuncAttributeMaxDynamicSharedMemorySize, ke_smem);

    kA<<<NB, 1024>>>(x, wb_w, wb_b);
    dim3 gP(16, NB);
    kP<<<gP, 256>>>(x);
    kB<<<NB, 512>>>(memory, a1_wq, a1_bq, a1_wk, a1_bk, a1_wv, a1_bv,
                    a1_fc, a1_fcb, a1_lng, a1_lnb);
    dim3 gC(128, 2);
    kCm<<<gC, 256, kcm_smem>>>(a2_wq, a2_wk, a2_wv, a2_bq, a2_bk, a2_bv, pq, pk, pv);
    dim3 gD(8, 4, NB);
    kD<<<gD, 256, kd_smem>>>();
    dim3 gE(8, NB);
    kE2<<<gE, 256, ke_smem>>>(a2_fc, a2_fcb, a2_lng, a2_lnb, out);
}

// round 10
// speedup vs baseline: 1.5476x; 1.0296x over previous
#include <cuda_runtime.h>
#include <math.h>

#define NB   16
#define SEQ  1024
#define CH   64
#define NC   5
#define MD   96

// ---------------- scratch (device globals; no allocation) ----------------
__device__ float g_w1[NB*SEQ*NC];
__device__ float g_w2[NB*NC*SEQ];
__device__ float g_cf[NB*SEQ*CH];
__device__ float g_pool[NB*16*NC*64];   // pooling partials [b][st][n*64+c]
__device__ float g_q [NB*4*SEQ*64];   // [b][h][s][d']  (d pair-interleaved)
__device__ float g_k [NB*4*SEQ*64];   // [b][h][s][d']  (d pair-interleaved)
__device__ float g_v [NB*4*SEQ*64];   // [b][h][d][s]   (TRANSPOSED)
__device__ float g_o [NB*4*SEQ*64];

// ---------------- helpers ----------------
__device__ __forceinline__ float tf32r(float x){
    unsigned u; asm("cvt.rna.tf32.f32 %0, %1;" : "=r"(u) : "f"(x));
    return __uint_as_float(u);
}
__device__ __forceinline__ unsigned tf32u(float x){
    unsigned u; asm("cvt.rna.tf32.f32 %0, %1;" : "=r"(u) : "f"(x));
    return u;
}
__device__ __forceinline__ float fex2(float x){
    float r; asm("ex2.approx.ftz.f32 %0, %1;" : "=f"(r) : "f"(x));
    return r;
}
__device__ __forceinline__ void cp16(void* dst, const void* src){
    unsigned d = (unsigned)__cvta_generic_to_shared(dst);
    asm volatile("cp.async.cg.shared.global [%0], [%1], 16;" :: "r"(d), "l"(src));
}
#define CP_COMMIT asm volatile("cp.async.commit_group;")
#define CP_WAIT1  asm volatile("cp.async.wait_group 1;")

#define MMA_TF32(c0,c1,c2,c3,a0,a1,a2,a3,b0,b1)                               \
  asm volatile("mma.sync.aligned.m16n8k8.row.col.f32.tf32.tf32.f32 "          \
    "{%0,%1,%2,%3}, {%4,%5,%6,%7}, {%8,%9}, {%0,%1,%2,%3};"                   \
    : "+f"(c0),"+f"(c1),"+f"(c2),"+f"(c3)                                     \
    : "r"(a0),"r"(a1),"r"(a2),"r"(a3),"r"(b0),"r"(b1))

// ================= Kernel A: weight = xt@wb_w, both softmaxes =============
__global__ __launch_bounds__(1024) void kA(const float* __restrict__ x,
                                           const float* __restrict__ wbw,
                                           const float* __restrict__ wbb)
{
    const int b = blockIdx.x, s = threadIdx.x;
    __shared__ float ws[CH*NC];
    __shared__ float red[32*NC];
    __shared__ float Mx[NC], Sx[NC];
    if (s < CH*NC) ws[s] = wbw[s];
    __syncthreads();

    const float* xb = x + b*(CH*SEQ) + s;
    float w[NC];
    #pragma unroll
    for (int n=0;n<NC;n++) w[n] = wbb[n];
    #pragma unroll 8
    for (int c=0;c<CH;c++){
        float xv = xb[c<<10];
        #pragma unroll
        for (int n=0;n<NC;n++) w[n] = fmaf(xv, ws[c*NC+n], w[n]);
    }

    {
        float mx = w[0];
        #pragma unroll
        for (int n=1;n<NC;n++) mx = fmaxf(mx, w[n]);
        float e[NC], ssum = 0.f;
        #pragma unroll
        for (int n=0;n<NC;n++){ e[n] = __expf(w[n]-mx); ssum += e[n]; }
        float inv = 1.f/ssum;
        float* w1p = g_w1 + b*(SEQ*NC) + s*NC;
        #pragma unroll
        for (int n=0;n<NC;n++) w1p[n] = e[n]*inv;
    }

    const int lane = s & 31, wid = s >> 5;
    float r5[NC];
    #pragma unroll
    for (int n=0;n<NC;n++) r5[n] = w[n];
    #pragma unroll
    for (int off=16; off; off>>=1)
        #pragma unroll
        for (int n=0;n<NC;n++) r5[n] = fmaxf(r5[n], __shfl_xor_sync(0xffffffffu, r5[n], off));
    if (lane==0){
        #pragma unroll
        for (int n=0;n<NC;n++) red[wid*NC+n] = r5[n];
    }
    __syncthreads();
    if (wid==0){
        #pragma unroll
        for (int n=0;n<NC;n++) r5[n] = red[lane*NC+n];
        #pragma unroll
        for (int off=16; off; off>>=1)
            #pragma unroll
            for (int n=0;n<NC;n++) r5[n] = fmaxf(r5[n], __shfl_xor_sync(0xffffffffu, r5[n], off));
        if (lane==0){
            #pragma unroll
            for (int n=0;n<NC;n++) Mx[n] = r5[n];
        }
    }
    __syncthreads();
    float e2[NC];
    #pragma unroll
    for (int n=0;n<NC;n++){ e2[n] = __expf(w[n]-Mx[n]); r5[n] = e2[n]; }
    #pragma unroll
    for (int off=16; off; off>>=1)
        #pragma unroll
        for (int n=0;n<NC;n++) r5[n] += __shfl_xor_sync(0xffffffffu, r5[n], off);
    if (lane==0){
        #pragma unroll
        for (int n=0;n<NC;n++) red[wid*NC+n] = r5[n];
    }
    __syncthreads();
    if (wid==0){
        #pragma unroll
        for (int n=0;n<NC;n++) r5[n] = red[lane*NC+n];
        #pragma unroll
        for (int off=16; off; off>>=1)
            #pragma unroll
            for (int n=0;n<NC;n++) r5[n] += __shfl_xor_sync(0xffffffffu, r5[n], off);
        if (lane==0){
            #pragma unroll
            for (int n=0;n<NC;n++) Sx[n] = r5[n];
        }
    }
    __syncthreads();
    float* w2p = g_w2 + b*(NC*SEQ) + s;
    #pragma unroll
    for (int n=0;n<NC;n++) w2p[n<<10] = e2[n] / Sx[n];
}

// ====== Kernel P: parallel class pooling partials =========================
__global__ __launch_bounds__(256) void kP(const float* __restrict__ x)
{
    const int st = blockIdx.x, b = blockIdx.y, tid = threadIdx.x;
    __shared__ float xs[64*65];
    __shared__ float w2s[NC*64];
    const int s0 = st*64;
    #pragma unroll
    for (int i=0;i<16;i++){
        int idx = i*256 + tid;
        int c = idx>>6, sl = idx&63;
        xs[c*65+sl] = x[b*65536 + (c<<10) + s0 + sl];
    }
    for (int idx=tid; idx<NC*64; idx+=256)
        w2s[idx] = g_w2[b*5120 + ((idx>>6)<<10) + s0 + (idx&63)];
    __syncthreads();
    for (int idx=tid; idx<NC*64; idx+=256){
        const int n = idx>>6, c = idx&63;
        float a = 0.f;
        #pragma unroll 8
        for (int sl=0; sl<64; sl++) a = fmaf(w2s[n*64+sl], xs[c*65+sl], a);
        g_pool[(b*16+st)*320 + idx] = a;
    }
}

// ====== Kernel B: reduce pooling, MHA1 (5 tokens vs memory), redistribute ==
__global__ __launch_bounds__(512) void kB(
    const float* __restrict__ memory,
    const float* __restrict__ wq, const float* __restrict__ bq,
    const float* __restrict__ wk, const float* __restrict__ bk,
    const float* __restrict__ wv, const float* __restrict__ bv,
    const float* __restrict__ fc, const float* __restrict__ fcb,
    const float* __restrict__ lng, const float* __restrict__ lnb)
{
    const int b = blockIdx.x, tid = threadIdx.x;
    __shared__ float cf1s[NC*64];
    __shared__ float mems[NC*MD];
    __shared__ float qh[NC*MD], kh[NC*MD], vh[NC*64];
    __shared__ float Ssm[NC*NC];
    __shared__ float osm[NC*64];
    __shared__ float projs[NC*64];

    if (tid < 320){
        float acc = 0.f;
        #pragma unroll
        for (int st=0; st<16; st++) acc += g_pool[(b*16+st)*320 + tid];
        cf1s[tid] = acc;
    }
    if (tid < NC*MD) mems[tid] = memory[tid];
    __syncthreads();

    if (tid < 480){
        const int n = tid/96, j = tid - n*96;
        float q = bq[j];
        #pragma unroll
        for (int d=0; d<64; d++) q = fmaf(cf1s[n*64+d], wq[d*96+j], q);
        qh[tid] = q * 0.102062072615966f;
        float kk = bk[j];
        #pragma unroll
        for (int d=0; d<96; d++) kk = fmaf(mems[n*96+d], wk[d*96+j], kk);
        kh[tid] = kk;
    }
    if (tid < 320){
        const int n = tid>>6, c = tid&63;
        float vv = bv[c];
        #pragma unroll
        for (int d=0; d<96; d++) vv = fmaf(mems[n*96+d], wv[d*64+c], vv);
        vh[tid] = vv;
    }
    __syncthreads();

    if (tid < 25){
        const int i = tid/5, j = tid - (tid/5)*5;
        float sv = 0.f;
        #pragma unroll
        for (int d=0; d<96; d++) sv = fmaf(qh[i*96+d], kh[j*96+d], sv);
        Ssm[tid] = sv;
    }
    __syncthreads();
    if (tid < 5){
        float m = Ssm[tid*5];
        #pragma unroll
        for (int j=1;j<5;j++) m = fmaxf(m, Ssm[tid*5+j]);
        float p[5], sum = 0.f;
        #pragma unroll
        for (int j=0;j<5;j++){ p[j] = __expf(Ssm[tid*5+j]-m); sum += p[j]; }
        float inv = 1.f/sum;
        #pragma unroll
        for (int j=0;j<5;j++) Ssm[tid*5+j] = p[j]*inv;
    }
    __syncthreads();
    if (tid < 320){
        const int n = tid>>6, c = tid&63;
        float o = 0.f;
        #pragma unroll
        for (int j=0;j<5;j++) o = fmaf(Ssm[n*5+j], vh[j*64+c], o);
        osm[tid] = o;
    }
    __syncthreads();
    if (tid < 320){
        const int n = tid>>6, c = tid&63;
        float p = fcb[c] + cf1s[tid];
        #pragma unroll
        for (int k=0;k<64;k++) p = fmaf(osm[n*64+k], fc[k*64+c], p);
        projs[tid] = p;
    }
    __syncthreads();
    if (tid < 160){
        const int n = tid>>5, lane = tid&31;
        float v0 = projs[n*64+lane], v1 = projs[n*64+lane+32];
        float sm = v0+v1, sq = v0*v0 + v1*v1;
        #pragma unroll
        for (int off=16; off; off>>=1){
            sm += __shfl_xor_sync(0xffffffffu, sm, off);
            sq += __shfl_xor_sync(0xffffffffu, sq, off);
        }
        float mu = sm*(1.f/64.f);
        float var = sq*(1.f/64.f) - mu*mu;
        float rs = rsqrtf(var + 1e-6f);
        cf1s[n*64+lane]    = (v0-mu)*rs*lng[lane]    + lnb[lane];
        cf1s[n*64+lane+32] = (v1-mu)*rs*lng[lane+32] + lnb[lane+32];
    }
    __syncthreads();
    for (int it=0; it<128; it++){
        int idx = it*512 + tid;
        int s = idx>>6, c = idx&63;
        const float* w1p = g_w1 + b*5120 + s*5;
        float a = 0.f;
        #pragma unroll
        for (int n=0;n<5;n++) a = fmaf(w1p[n], cf1s[n*64+c], a);
        g_cf[b*65536 + idx] = a;
    }
}

// ====== Kernel Cm: fused QKV projection via tf32 mma, z fused in-CTA ======
__global__ __launch_bounds__(256) void kCm(
    const float* __restrict__ wq, const float* __restrict__ wk, const float* __restrict__ wv,
    const float* __restrict__ bq, const float* __restrict__ bk, const float* __restrict__ bv,
    float* __restrict__ pq, float* __restrict__ pk, float* __restrict__ pv)
{
    extern __shared__ float smc[];
    float* Ast = smc;          // [128][68]
    float* Ws  = smc + 8704;   // [64][136]
    float* bs  = smc + 17408;  // [128]
    const int mt=blockIdx.x, nt=blockIdx.y;
    const int tid=threadIdx.x, w=tid>>5, lane=tid&31, gid=lane>>2, l4=lane&3;

    const float* Ap = g_cf + mt*128*64;
    #pragma unroll
    for (int i=0;i<8;i++){
        int idx=i*256+tid, row=idx>>4, c4=(idx&15)*4;
        *(float4*)(Ast + row*68 + c4) = *(const float4*)(Ap + row*64 + c4);
    }
    __syncthreads();

    unsigned af[8][4];
    const int r0 = w*16;
    #pragma unroll
    for (int kk=0;kk<8;kk++){
        af[kk][0]=__float_as_uint(Ast[(r0+gid  )*68 + kk*8   + l4]);
        af[kk][1]=__float_as_uint(Ast[(r0+gid+8)*68 + kk*8   + l4]);
        af[kk][2]=__float_as_uint(Ast[(r0+gid  )*68 + kk*8+4 + l4]);
        af[kk][3]=__float_as_uint(Ast[(r0+gid+8)*68 + kk*8+4 + l4]);
    }

    const int row_lo = mt*128 + r0 + gid;
    const int bidx = row_lo>>10, s_lo = row_lo&1023;

    #pragma unroll
    for (int z=0; z<3; z++){
        const float* W  = (z==0)?wq:((z==1)?wk:wv);
        const float* Bp = (z==0)?bq:((z==1)?bk:bv);
        float*       O  = (z==0)?pq:((z==1)?pk:pv);

        __syncthreads();   // prior z's readers done with Ws
        #pragma unroll
        for (int i=0;i<8;i++){
            int idx=i*256+tid, row=idx>>5, c4=(idx&31)*4;
            *(float4*)(Ws + row*136 + c4) = *(const float4*)(W + row*256 + nt*128 + c4);
        }
        if (tid<128) bs[tid] = Bp[nt*128+tid];
        __syncthreads();

        float c[16][4];
        #pragma unroll
        for (int j=0;j<16;j++){ c[j][0]=c[j][1]=c[j][2]=c[j][3]=0.f; }
        #pragma unroll
        for (int j=0;j<16;j++){
            #pragma unroll
            for (int kk=0;kk<8;kk++){
                unsigned b0=__float_as_uint(Ws[(kk*8+l4  )*136 + j*8+gid]);
                unsigned b1=__float_as_uint(Ws[(kk*8+l4+4)*136 + j*8+gid]);
                MMA_TF32(c[j][0],c[j][1],c[j][2],c[j][3],
                         af[kk][0],af[kk][1],af[kk][2],af[kk][3],b0,b1);
            }
        }
        #pragma unroll
        for (int j=0;j<16;j++){
            int cl = j*8 + 2*l4;
            int col0 = nt*128 + cl;
            int h = col0>>6, d0 = col0&63, d1 = d0+1;
            float* op = O + (((bidx<<2)+h)<<16);
            float v00 = tf32r(c[j][0]+bs[cl]);
            float v01 = tf32r(c[j][1]+bs[cl+1]);
            float v10 = tf32r(c[j][2]+bs[cl]);
            float v11 = tf32r(c[j][3]+bs[cl+1]);
            if (z < 2){
                int dp0 = (d0&56)|((d0&3)<<1)|((d0&4)>>2);
                int dp1 = (d1&56)|((d1&3)<<1)|((d1&4)>>2);
                op[ s_lo   *64 + dp0] = v00;
                op[ s_lo   *64 + dp1] = v01;
                op[(s_lo+8)*64 + dp0] = v10;
                op[(s_lo+8)*64 + dp1] = v11;
            } else {
                op[d0*1024 + s_lo  ] = v00;
                op[d1*1024 + s_lo  ] = v01;
                op[d0*1024 + s_lo+8] = v10;
                op[d1*1024 + s_lo+8] = v11;
            }
        }
    }
}

// ========== Kernel D: tf32 mma flash attention, M=32/warp ================
// 128 threads / 4 warps; each warp owns 32 q-rows as two m16 tiles, so every
// B-fragment LDS is reused for 2 mma -> per-CTA smem read traffic halved.
// K/V tiles 64 rows, pad 72, double-buffered depth-2 cp.async.
__global__ __launch_bounds__(128, 2) void kD()
{
    extern __shared__ float sm[];
    float* KS0 = sm;             // [64][72]
    float* VS0 = sm + 4608;      // [64][72]  (V^T tile: [d][s])
    float* KS1 = sm + 9216;      // [64][72]
    float* VS1 = sm + 13824;     // [64][72]
    float* Qst = sm;             // alias [128][72] (used before K/V loads)

    const int qt=blockIdx.x, h=blockIdx.y, b=blockIdx.z;
    const int tid=threadIdx.x, w=tid>>5, lane=tid&31;
    const int gid=lane>>2, l4=lane&3;
    const int base=((b*4+h)<<16);

    const float* Kg = g_k + base;
    const float* Vg = g_v + base;          // [64 d][1024 s]
    const float* Qg = g_q + base + qt*8192;

    // stage Q scaled by log2(e)/sqrt(64) so softmax uses bare ex2
    const float QSC = 0.125f * 1.4426950408889634f;
    #pragma unroll
    for (int i=0;i<16;i++){
        int idx=i*128+tid, row=idx>>4, c4=(idx&15)*4;
        float4 v = *(const float4*)(Qg + row*64 + c4);
        Qst[row*72+c4+0]=v.x*QSC; Qst[row*72+c4+1]=v.y*QSC;
        Qst[row*72+c4+2]=v.z*QSC; Qst[row*72+c4+3]=v.w*QSC;
    }
    __syncthreads();
    unsigned qf[2][8][4];
    const int r0 = w*32;
    #pragma unroll
    for (int mt=0;mt<2;mt++){
        const int rb = r0 + mt*16;
        #pragma unroll
        for (int kk=0;kk<8;kk++){
            float2 lo = *(const float2*)(Qst + (rb+gid  )*72 + kk*8 + 2*l4);
            float2 hi = *(const float2*)(Qst + (rb+gid+8)*72 + kk*8 + 2*l4);
            qf[mt][kk][0]=__float_as_uint(lo.x); qf[mt][kk][1]=__float_as_uint(hi.x);
            qf[mt][kk][2]=__float_as_uint(lo.y); qf[mt][kk][3]=__float_as_uint(hi.y);
        }
    }
    __syncthreads();   // done reading Qst before K/V overwrite

    #pragma unroll
    for (int i=0;i<8;i++){
        int idx=i*128+tid, row=idx>>4, c4=(idx&15)*4;
        cp16(KS0 + row*72 + c4, Kg + row*64 + c4);
        cp16(VS0 + row*72 + c4, Vg + row*1024 + c4);
    }
    CP_COMMIT;
    #pragma unroll
    for (int i=0;i<8;i++){
        int idx=i*128+tid, row=idx>>4, c4=(idx&15)*4;
        cp16(KS1 + row*72 + c4, Kg + 4096 + row*64 + c4);
        cp16(VS1 + row*72 + c4, Vg + 64 + row*1024 + c4);
    }
    CP_COMMIT;

    float o0[8][4], o1[8][4];
    #pragma unroll
    for (int n=0;n<8;n++){
        o0[n][0]=o0[n][1]=o0[n][2]=o0[n][3]=0.f;
        o1[n][0]=o1[n][1]=o1[n][2]=o1[n][3]=0.f;
    }
    float m_lo0=-1e30f, m_hi0=-1e30f, l_lo0=0.f, l_hi0=0.f;
    float m_lo1=-1e30f, m_hi1=-1e30f, l_lo1=0.f, l_hi1=0.f;

    for (int kt=0; kt<16; kt++){
        CP_WAIT1;
        __syncthreads();
        const float* Ks_ = (kt&1) ? KS1 : KS0;
        const float* Vs_ = (kt&1) ? VS1 : VS0;

        // ---- S = Q K^T : B-frag loaded once, used by both m-tiles ----
        float c0[8][4], c1[8][4];
        #pragma unroll
        for (int j=0;j<8;j++){
            c0[j][0]=c0[j][1]=c0[j][2]=c0[j][3]=0.f;
            c1[j][0]=c1[j][1]=c1[j][2]=c1[j][3]=0.f;
        }
        #pragma unroll
        for (int j=0;j<8;j++){
            #pragma unroll
            for (int kk=0;kk<8;kk++){
                float2 bb = *(const float2*)(Ks_ + (j*8+gid)*72 + kk*8 + 2*l4);
                unsigned ub0=__float_as_uint(bb.x), ub1=__float_as_uint(bb.y);
                MMA_TF32(c0[j][0],c0[j][1],c0[j][2],c0[j][3],
                         qf[0][kk][0],qf[0][kk][1],qf[0][kk][2],qf[0][kk][3],ub0,ub1);
                MMA_TF32(c1[j][0],c1[j][1],c1[j][2],c1[j][3],
                         qf[1][kk][0],qf[1][kk][1],qf[1][kk][2],qf[1][kk][3],ub0,ub1);
            }
        }

        // ---- online softmax (base-2), per m-tile ----
        {
            float mx_lo=-1e30f, mx_hi=-1e30f;
            #pragma unroll
            for (int j=0;j<8;j++){
                mx_lo = fmaxf(mx_lo, fmaxf(c0[j][0], c0[j][1]));
                mx_hi = fmaxf(mx_hi, fmaxf(c0[j][2], c0[j][3]));
            }
            mx_lo = fmaxf(mx_lo, __shfl_xor_sync(0xffffffffu, mx_lo, 1));
            mx_lo = fmaxf(mx_lo, __shfl_xor_sync(0xffffffffu, mx_lo, 2));
            mx_hi = fmaxf(mx_hi, __shfl_xor_sync(0xffffffffu, mx_hi, 1));
            mx_hi = fmaxf(mx_hi, __shfl_xor_sync(0xffffffffu, mx_hi, 2));
            float mn_lo = fmaxf(m_lo0, mx_lo), mn_hi = fmaxf(m_hi0, mx_hi);
            float al = fex2(m_lo0 - mn_lo), ah = fex2(m_hi0 - mn_hi);
            float s_lo=0.f, s_hi=0.f;
            #pragma unroll
            for (int j=0;j<8;j++){
                c0[j][0]=fex2(c0[j][0]-mn_lo); s_lo+=c0[j][0];
                c0[j][1]=fex2(c0[j][1]-mn_lo); s_lo+=c0[j][1];
                c0[j][2]=fex2(c0[j][2]-mn_hi); s_hi+=c0[j][2];
                c0[j][3]=fex2(c0[j][3]-mn_hi); s_hi+=c0[j][3];
            }
            s_lo += __shfl_xor_sync(0xffffffffu, s_lo, 1);
            s_lo += __shfl_xor_sync(0xffffffffu, s_lo, 2);
            s_hi += __shfl_xor_sync(0xffffffffu, s_hi, 1);
            s_hi += __shfl_xor_sync(0xffffffffu, s_hi, 2);
            l_lo0 = l_lo0*al + s_lo;  l_hi0 = l_hi0*ah + s_hi;
            m_lo0 = mn_lo;            m_hi0 = mn_hi;
            #pragma unroll
            for (int n=0;n<8;n++){
                o0[n][0]*=al; o0[n][1]*=al; o0[n][2]*=ah; o0[n][3]*=ah;
            }
        }
        {
            float mx_lo=-1e30f, mx_hi=-1e30f;
            #pragma unroll
            for (int j=0;j<8;j++){
                mx_lo = fmaxf(mx_lo, fmaxf(c1[j][0], c1[j][1]));
                mx_hi = fmaxf(mx_hi, fmaxf(c1[j][2], c1[j][3]));
            }
            mx_lo = fmaxf(mx_lo, __shfl_xor_sync(0xffffffffu, mx_lo, 1));
            mx_lo = fmaxf(mx_lo, __shfl_xor_sync(0xffffffffu, mx_lo, 2));
            mx_hi = fmaxf(mx_hi, __shfl_xor_sync(0xffffffffu, mx_hi, 1));
            mx_hi = fmaxf(mx_hi, __shfl_xor_sync(0xffffffffu, mx_hi, 2));
            float mn_lo = fmaxf(m_lo1, mx_lo), mn_hi = fmaxf(m_hi1, mx_hi);
            float al = fex2(m_lo1 - mn_lo), ah = fex2(m_hi1 - mn_hi);
            float s_lo=0.f, s_hi=0.f;
            #pragma unroll
            for (int j=0;j<8;j++){
                c1[j][0]=fex2(c1[j][0]-mn_lo); s_lo+=c1[j][0];
                c1[j][1]=fex2(c1[j][1]-mn_lo); s_lo+=c1[j][1];
                c1[j][2]=fex2(c1[j][2]-mn_hi); s_hi+=c1[j][2];
                c1[j][3]=fex2(c1[j][3]-mn_hi); s_hi+=c1[j][3];
            }
            s_lo += __shfl_xor_sync(0xffffffffu, s_lo, 1);
            s_lo += __shfl_xor_sync(0xffffffffu, s_lo, 2);
            s_hi += __shfl_xor_sync(0xffffffffu, s_hi, 1);
            s_hi += __shfl_xor_sync(0xffffffffu, s_hi, 2);
            l_lo1 = l_lo1*al + s_lo;  l_hi1 = l_hi1*ah + s_hi;
            m_lo1 = mn_lo;            m_hi1 = mn_hi;
            #pragma unroll
            for (int n=0;n<8;n++){
                o1[n][0]*=al; o1[n][1]*=al; o1[n][2]*=ah; o1[n][3]*=ah;
            }
        }

        // ---- O += P V : P A-frags direct from S accum; V B-frag reused ----
        #pragma unroll
        for (int t=0;t<8;t++){
            unsigned a00 = tf32u(c0[t][0]);
            unsigned a01 = tf32u(c0[t][2]);
            unsigned a02 = tf32u(c0[t][1]);
            unsigned a03 = tf32u(c0[t][3]);
            unsigned a10 = tf32u(c1[t][0]);
            unsigned a11 = tf32u(c1[t][2]);
            unsigned a12 = tf32u(c1[t][1]);
            unsigned a13 = tf32u(c1[t][3]);
            #pragma unroll
            for (int n=0;n<8;n++){
                float2 bb = *(const float2*)(Vs_ + (n*8+gid)*72 + t*8 + 2*l4);
                unsigned ub0=__float_as_uint(bb.x), ub1=__float_as_uint(bb.y);
                MMA_TF32(o0[n][0],o0[n][1],o0[n][2],o0[n][3],a00,a01,a02,a03,ub0,ub1);
                MMA_TF32(o1[n][0],o1[n][1],o1[n][2],o1[n][3],a10,a11,a12,a13,ub0,ub1);
            }
        }

        __syncthreads();
        if (kt < 14){
            const float* Kp = Kg + (kt+2)*4096;
            const float* Vp = Vg + (kt+2)*64;
            float* kd = (kt&1) ? KS1 : KS0;
            float* vd = (kt&1) ? VS1 : VS0;
            #pragma unroll
            for (int i=0;i<8;i++){
                int idx=i*128+tid, row=idx>>4, c4=(idx&15)*4;
                cp16(kd + row*72 + c4, Kp + row*64 + c4);
                cp16(vd + row*72 + c4, Vp + row*1024 + c4);
            }
        }
        CP_COMMIT;
    }

    float* Op = g_o + base + qt*8192;
    {
        float il = 1.f/l_lo0, ih = 1.f/l_hi0;
        const int r_lo = r0 + gid, r_hi = r_lo + 8;
        #pragma unroll
        for (int n=0;n<8;n++){
            int col = n*8 + 2*l4;
            *(float2*)(Op + r_lo*64 + col) = make_float2(o0[n][0]*il, o0[n][1]*il);
            *(float2*)(Op + r_hi*64 + col) = make_float2(o0[n][2]*ih, o0[n][3]*ih);
        }
    }
    {
        float il = 1.f/l_lo1, ih = 1.f/l_hi1;
        const int r_lo = r0 + 16 + gid, r_hi = r_lo + 8;
        #pragma unroll
        for (int n=0;n<8;n++){
            int col = n*8 + 2*l4;
            *(float2*)(Op + r_lo*64 + col) = make_float2(o1[n][0]*il, o1[n][1]*il);
            *(float2*)(Op + r_hi*64 + col) = make_float2(o1[n][2]*ih, o1[n][3]*ih);
        }
    }
}

// ==== Kernel E2: tf32 mma out-proj + residual + LN + transpose ============
__global__ __launch_bounds__(256) void kE2(const float* __restrict__ fc,
                                           const float* __restrict__ fcb,
                                           const float* __restrict__ lng,
                                           const float* __restrict__ lnb,
                                           float* __restrict__ out)
{
    extern __shared__ float sme[];
    float* As = sme;           // [128][68] GEMM phase; Cs [128][69] epilogue
    float* Bs = sme + 8832;    // [64][68]
    float* Cs = sme;
    const int stile = blockIdx.x, b = blockIdx.y, tid = threadIdx.x;
    const int w=tid>>5, lane=tid&31, gid=lane>>2, l4=lane&3;
    const int r0 = w*16;
    const int s0 = stile*128;

    float c[8][4];
    #pragma unroll
    for (int j=0;j<8;j++){ c[j][0]=c[j][1]=c[j][2]=c[j][3]=0.f; }

    for (int h=0; h<4; h++){
        __syncthreads();
        const float* Ap = g_o + ((b*4+h)<<16) + s0*64;
        #pragma unroll
        for (int i=0;i<8;i++){
            int idx=i*256+tid, row=idx>>4, c4=(idx&15)*4;
            *(float4*)(As + row*68 + c4) = *(const float4*)(Ap + row*64 + c4);
        }
        #pragma unroll
        for (int i=0;i<4;i++){
            int idx=i*256+tid, row=idx>>4, c4=(idx&15)*4;
            *(float4*)(Bs + row*68 + c4) = *(const float4*)(fc + (h*64+row)*64 + c4);
        }
        __syncthreads();
        unsigned af[8][4];
        #pragma unroll
        for (int kk=0;kk<8;kk++){
            af[kk][0]=__float_as_uint(As[(r0+gid  )*68 + kk*8   + l4]);
            af[kk][1]=__float_as_uint(As[(r0+gid+8)*68 + kk*8   + l4]);
            af[kk][2]=__float_as_uint(As[(r0+gid  )*68 + kk*8+4 + l4]);
            af[kk][3]=__float_as_uint(As[(r0+gid+8)*68 + kk*8+4 + l4]);
        }
        #pragma unroll
        for (int j=0;j<8;j++){
            #pragma unroll
            for (int kk=0;kk<8;kk++){
                unsigned b0=__float_as_uint(Bs[(kk*8+l4  )*68 + j*8+gid]);
                unsigned b1=__float_as_uint(Bs[(kk*8+l4+4)*68 + j*8+gid]);
                MMA_TF32(c[j][0],c[j][1],c[j][2],c[j][3],
                         af[kk][0],af[kk][1],af[kk][2],af[kk][3],b0,b1);
            }
        }
    }
    __syncthreads();
    const int r_lo = r0 + gid, r_hi = r_lo + 8;
    #pragma unroll
    for (int j=0;j<8;j++){
        int col = j*8 + 2*l4;
        float b0 = fcb[col], b1 = fcb[col+1];
        Cs[r_lo*69+col  ] = c[j][0] + b0 + g_cf[b*65536 + (s0+r_lo)*64 + col  ];
        Cs[r_lo*69+col+1] = c[j][1] + b1 + g_cf[b*65536 + (s0+r_lo)*64 + col+1];
        Cs[r_hi*69+col  ] = c[j][2] + b0 + g_cf[b*65536 + (s0+r_hi)*64 + col  ];
        Cs[r_hi*69+col+1] = c[j][3] + b1 + g_cf[b*65536 + (s0+r_hi)*64 + col+1];
    }
    __syncthreads();
    for (int rr=0; rr<16; rr++){
        int r = w*16 + rr;
        float v0 = Cs[r*69+lane], v1 = Cs[r*69+lane+32];
        float sm = v0+v1, sq = v0*v0 + v1*v1;
        #pragma unroll
        for (int off=16; off; off>>=1){
            sm += __shfl_xor_sync(0xffffffffu, sm, off);
            sq += __shfl_xor_sync(0xffffffffu, sq, off);
        }
        float mu = sm*(1.f/64.f);
        float var = sq*(1.f/64.f) - mu*mu;
        float rstd = rsqrtf(var + 1e-6f);
        Cs[r*69+lane]    = (v0-mu)*rstd*lng[lane]    + lnb[lane];
        Cs[r*69+lane+32] = (v1-mu)*rstd*lng[lane+32] + lnb[lane+32];
    }
    __syncthreads();
    #pragma unroll
    for (int i=0;i<32;i++){
        int idx = i*256 + tid;
        int cc = idx>>7, sl = idx&127;
        out[(((b<<6)+cc)<<10) + s0 + sl] = Cs[sl*69+cc];
    }
}

// ============================== launcher ===================================
extern "C" void kernel_launch(void* const* d_in, const int* in_sizes, int n_in,
                              void* d_out, int out_size)
{
    const float* x      = (const float*)d_in[0];
    const float* memory = (const float*)d_in[1];
    const float* wb_w   = (const float*)d_in[2];
    const float* wb_b   = (const float*)d_in[3];
    const float* a1_wq  = (const float*)d_in[4];
    const float* a1_bq  = (const float*)d_in[5];
    const float* a1_wk  = (const float*)d_in[6];
    const float* a1_bk  = (const float*)d_in[7];
    const float* a1_wv  = (const float*)d_in[8];
    const float* a1_bv  = (const float*)d_in[9];
    const float* a1_fc  = (const float*)d_in[10];
    const float* a1_fcb = (const float*)d_in[11];
    const float* a1_lng = (const float*)d_in[12];
    const float* a1_lnb = (const float*)d_in[13];
    const float* a2_wq  = (const float*)d_in[14];
    const float* a2_bq  = (const float*)d_in[15];
    const float* a2_wk  = (const float*)d_in[16];
    const float* a2_bk  = (const float*)d_in[17];
    const float* a2_wv  = (const float*)d_in[18];
    const float* a2_bv  = (const float*)d_in[19];
    const float* a2_fc  = (const float*)d_in[20];
    const float* a2_fcb = (const float*)d_in[21];
    const float* a2_lng = (const float*)d_in[22];
    const float* a2_lnb = (const float*)d_in[23];
    float* out = (float*)d_out;

    float *pq=0, *pk=0, *pv=0;
    cudaGetSymbolAddress((void**)&pq, g_q);
    cudaGetSymbolAddress((void**)&pk, g_k);
    cudaGetSymbolAddress((void**)&pv, g_v);

    const int kcm_smem = 17536*4;          // 70144 B
    const int kd_smem  = 18432*4;          // 73728 B -> 2 CTAs/SM
    const int ke_smem  = (8832+4352)*4;    // 52736 B
    cudaFuncSetAttribute(kCm, cudaFuncAttributeMaxDynamicSharedMemorySize, kcm_smem);
    cudaFuncSetAttribute(kD,  cudaFuncAttributeMaxDynamicSharedMemorySize, kd_smem);
    cudaFuncSetAttribute(kE2, cudaFuncAttributeMaxDynamicSharedMemorySize, ke_smem);

    kA<<<NB, 1024>>>(x, wb_w, wb_b);
    dim3 gP(16, NB);
    kP<<<gP, 256>>>(x);
    kB<<<NB, 512>>>(memory, a1_wq, a1_bq, a1_wk, a1_bk, a1_wv, a1_bv,
                    a1_fc, a1_fcb, a1_lng, a1_lnb);
    dim3 gC(128, 2);
    kCm<<<gC, 256, kcm_smem>>>(a2_wq, a2_wk, a2_wv, a2_bq, a2_bk, a2_bv, pq, pk, pv);
    dim3 gD(8, 4, NB);
    kD<<<gD, 128, kd_smem>>>();
    dim3 gE(8, NB);
    kE2<<<gE, 256, ke_smem>>>(a2_fc, a2_fcb, a2_lng, a2_lnb, out);
}

// round 11
// speedup vs baseline: 1.9895x; 1.2855x over previous
#include <cuda_runtime.h>
#include <cuda_fp16.h>
#include <math.h>

#define NB   16
#define SEQ  1024
#define CH   64
#define NC   5
#define MD   96

// ---------------- scratch (device globals; no allocation) ----------------
__device__ float g_w1[NB*SEQ*NC];
__device__ float g_w2[NB*NC*SEQ];
__device__ float g_cf[NB*SEQ*CH];
__device__ float g_pool[NB*16*NC*64];
// fp16 Q/K/V. Q,K: [b][h][s][d~] with d perm16'd within 16-groups, Q pre-scaled
// by log2(e)/8. V: [b][h][d][s~] transposed with s perm16'd within 16-groups.
__device__ __align__(16) __half g_q[NB*4*SEQ*64];
__device__ __align__(16) __half g_k[NB*4*SEQ*64];
__device__ __align__(16) __half g_v[NB*4*SEQ*64];
__device__ float g_o[NB*4*SEQ*64];

// ---------------- helpers ----------------
__device__ __forceinline__ float fex2(float x){
    float r; asm("ex2.approx.ftz.f32 %0, %1;" : "=f"(r) : "f"(x));
    return r;
}
__device__ __forceinline__ unsigned pack_h2(float lo, float hi){
    unsigned r; asm("cvt.rn.f16x2.f32 %0, %1, %2;" : "=r"(r) : "f"(hi), "f"(lo));
    return r;
}
// within each 16-group: pair q -> slot 2*(q&3)+(q>>2); pairs stay adjacent.
__device__ __forceinline__ int perm16(int k){
    int g = k & ~15, r = k & 15, q = r >> 1, odd = k & 1;
    int slot = ((q & 3) << 1) | (q >> 2);
    return g | (slot << 1) | odd;
}
__device__ __forceinline__ void cp16(void* dst, const void* src){
    unsigned d = (unsigned)__cvta_generic_to_shared(dst);
    asm volatile("cp.async.cg.shared.global [%0], [%1], 16;" :: "r"(d), "l"(src));
}
#define CP_COMMIT asm volatile("cp.async.commit_group;")
#define CP_WAIT1  asm volatile("cp.async.wait_group 1;")

#define MMA_TF32(c0,c1,c2,c3,a0,a1,a2,a3,b0,b1)                               \
  asm volatile("mma.sync.aligned.m16n8k8.row.col.f32.tf32.tf32.f32 "          \
    "{%0,%1,%2,%3}, {%4,%5,%6,%7}, {%8,%9}, {%0,%1,%2,%3};"                   \
    : "+f"(c0),"+f"(c1),"+f"(c2),"+f"(c3)                                     \
    : "r"(a0),"r"(a1),"r"(a2),"r"(a3),"r"(b0),"r"(b1))

#define MMA_F16(c0,c1,c2,c3,a0,a1,a2,a3,b0,b1)                                \
  asm volatile("mma.sync.aligned.m16n8k16.row.col.f32.f16.f16.f32 "           \
    "{%0,%1,%2,%3}, {%4,%5,%6,%7}, {%8,%9}, {%0,%1,%2,%3};"                   \
    : "+f"(c0),"+f"(c1),"+f"(c2),"+f"(c3)                                     \
    : "r"(a0),"r"(a1),"r"(a2),"r"(a3),"r"(b0),"r"(b1))

// ================= Kernel A: weight = xt@wb_w, both softmaxes =============
__global__ __launch_bounds__(1024) void kA(const float* __restrict__ x,
                                           const float* __restrict__ wbw,
                                           const float* __restrict__ wbb)
{
    const int b = blockIdx.x, s = threadIdx.x;
    __shared__ float ws[CH*NC];
    __shared__ float red[32*NC];
    __shared__ float Mx[NC], Sx[NC];
    if (s < CH*NC) ws[s] = wbw[s];
    __syncthreads();

    const float* xb = x + b*(CH*SEQ) + s;
    float w[NC];
    #pragma unroll
    for (int n=0;n<NC;n++) w[n] = wbb[n];
    #pragma unroll 8
    for (int c=0;c<CH;c++){
        float xv = xb[c<<10];
        #pragma unroll
        for (int n=0;n<NC;n++) w[n] = fmaf(xv, ws[c*NC+n], w[n]);
    }

    {
        float mx = w[0];
        #pragma unroll
        for (int n=1;n<NC;n++) mx = fmaxf(mx, w[n]);
        float e[NC], ssum = 0.f;
        #pragma unroll
        for (int n=0;n<NC;n++){ e[n] = __expf(w[n]-mx); ssum += e[n]; }
        float inv = 1.f/ssum;
        float* w1p = g_w1 + b*(SEQ*NC) + s*NC;
        #pragma unroll
        for (int n=0;n<NC;n++) w1p[n] = e[n]*inv;
    }

    const int lane = s & 31, wid = s >> 5;
    float r5[NC];
    #pragma unroll
    for (int n=0;n<NC;n++) r5[n] = w[n];
    #pragma unroll
    for (int off=16; off; off>>=1)
        #pragma unroll
        for (int n=0;n<NC;n++) r5[n] = fmaxf(r5[n], __shfl_xor_sync(0xffffffffu, r5[n], off));
    if (lane==0){
        #pragma unroll
        for (int n=0;n<NC;n++) red[wid*NC+n] = r5[n];
    }
    __syncthreads();
    if (wid==0){
        #pragma unroll
        for (int n=0;n<NC;n++) r5[n] = red[lane*NC+n];
        #pragma unroll
        for (int off=16; off; off>>=1)
            #pragma unroll
            for (int n=0;n<NC;n++) r5[n] = fmaxf(r5[n], __shfl_xor_sync(0xffffffffu, r5[n], off));
        if (lane==0){
            #pragma unroll
            for (int n=0;n<NC;n++) Mx[n] = r5[n];
        }
    }
    __syncthreads();
    float e2[NC];
    #pragma unroll
    for (int n=0;n<NC;n++){ e2[n] = __expf(w[n]-Mx[n]); r5[n] = e2[n]; }
    #pragma unroll
    for (int off=16; off; off>>=1)
        #pragma unroll
        for (int n=0;n<NC;n++) r5[n] += __shfl_xor_sync(0xffffffffu, r5[n], off);
    if (lane==0){
        #pragma unroll
        for (int n=0;n<NC;n++) red[wid*NC+n] = r5[n];
    }
    __syncthreads();
    if (wid==0){
        #pragma unroll
        for (int n=0;n<NC;n++) r5[n] = red[lane*NC+n];
        #pragma unroll
        for (int off=16; off; off>>=1)
            #pragma unroll
            for (int n=0;n<NC;n++) r5[n] += __shfl_xor_sync(0xffffffffu, r5[n], off);
        if (lane==0){
            #pragma unroll
            for (int n=0;n<NC;n++) Sx[n] = r5[n];
        }
    }
    __syncthreads();
    float* w2p = g_w2 + b*(NC*SEQ) + s;
    #pragma unroll
    for (int n=0;n<NC;n++) w2p[n<<10] = e2[n] / Sx[n];
}

// ====== Kernel P: parallel class pooling partials =========================
__global__ __launch_bounds__(256) void kP(const float* __restrict__ x)
{
    const int st = blockIdx.x, b = blockIdx.y, tid = threadIdx.x;
    __shared__ float xs[64*65];
    __shared__ float w2s[NC*64];
    const int s0 = st*64;
    #pragma unroll
    for (int i=0;i<16;i++){
        int idx = i*256 + tid;
        int c = idx>>6, sl = idx&63;
        xs[c*65+sl] = x[b*65536 + (c<<10) + s0 + sl];
    }
    for (int idx=tid; idx<NC*64; idx+=256)
        w2s[idx] = g_w2[b*5120 + ((idx>>6)<<10) + s0 + (idx&63)];
    __syncthreads();
    for (int idx=tid; idx<NC*64; idx+=256){
        const int n = idx>>6, c = idx&63;
        float a = 0.f;
        #pragma unroll 8
        for (int sl=0; sl<64; sl++) a = fmaf(w2s[n*64+sl], xs[c*65+sl], a);
        g_pool[(b*16+st)*320 + idx] = a;
    }
}

// ====== Kernel B: reduce pooling, MHA1 (5 tokens vs memory), redistribute ==
__global__ __launch_bounds__(512) void kB(
    const float* __restrict__ memory,
    const float* __restrict__ wq, const float* __restrict__ bq,
    const float* __restrict__ wk, const float* __restrict__ bk,
    const float* __restrict__ wv, const float* __restrict__ bv,
    const float* __restrict__ fc, const float* __restrict__ fcb,
    const float* __restrict__ lng, const float* __restrict__ lnb)
{
    const int b = blockIdx.x, tid = threadIdx.x;
    __shared__ float cf1s[NC*64];
    __shared__ float mems[NC*MD];
    __shared__ float qh[NC*MD], kh[NC*MD], vh[NC*64];
    __shared__ float Ssm[NC*NC];
    __shared__ float osm[NC*64];
    __shared__ float projs[NC*64];

    if (tid < 320){
        float acc = 0.f;
        #pragma unroll
        for (int st=0; st<16; st++) acc += g_pool[(b*16+st)*320 + tid];
        cf1s[tid] = acc;
    }
    if (tid < NC*MD) mems[tid] = memory[tid];
    __syncthreads();

    if (tid < 480){
        const int n = tid/96, j = tid - n*96;
        float q = bq[j];
        #pragma unroll
        for (int d=0; d<64; d++) q = fmaf(cf1s[n*64+d], wq[d*96+j], q);
        qh[tid] = q * 0.102062072615966f;
        float kk = bk[j];
        #pragma unroll
        for (int d=0; d<96; d++) kk = fmaf(mems[n*96+d], wk[d*96+j], kk);
        kh[tid] = kk;
    }
    if (tid < 320){
        const int n = tid>>6, c = tid&63;
        float vv = bv[c];
        #pragma unroll
        for (int d=0; d<96; d++) vv = fmaf(mems[n*96+d], wv[d*64+c], vv);
        vh[tid] = vv;
    }
    __syncthreads();

    if (tid < 25){
        const int i = tid/5, j = tid - (tid/5)*5;
        float sv = 0.f;
        #pragma unroll
        for (int d=0; d<96; d++) sv = fmaf(qh[i*96+d], kh[j*96+d], sv);
        Ssm[tid] = sv;
    }
    __syncthreads();
    if (tid < 5){
        float m = Ssm[tid*5];
        #pragma unroll
        for (int j=1;j<5;j++) m = fmaxf(m, Ssm[tid*5+j]);
        float p[5], sum = 0.f;
        #pragma unroll
        for (int j=0;j<5;j++){ p[j] = __expf(Ssm[tid*5+j]-m); sum += p[j]; }
        float inv = 1.f/sum;
        #pragma unroll
        for (int j=0;j<5;j++) Ssm[tid*5+j] = p[j]*inv;
    }
    __syncthreads();
    if (tid < 320){
        const int n = tid>>6, c = tid&63;
        float o = 0.f;
        #pragma unroll
        for (int j=0;j<5;j++) o = fmaf(Ssm[n*5+j], vh[j*64+c], o);
        osm[tid] = o;
    }
    __syncthreads();
    if (tid < 320){
        const int n = tid>>6, c = tid&63;
        float p = fcb[c] + cf1s[tid];
        #pragma unroll
        for (int k=0;k<64;k++) p = fmaf(osm[n*64+k], fc[k*64+c], p);
        projs[tid] = p;
    }
    __syncthreads();
    if (tid < 160){
        const int n = tid>>5, lane = tid&31;
        float v0 = projs[n*64+lane], v1 = projs[n*64+lane+32];
        float sm = v0+v1, sq = v0*v0 + v1*v1;
        #pragma unroll
        for (int off=16; off; off>>=1){
            sm += __shfl_xor_sync(0xffffffffu, sm, off);
            sq += __shfl_xor_sync(0xffffffffu, sq, off);
        }
        float mu = sm*(1.f/64.f);
        float var = sq*(1.f/64.f) - mu*mu;
        float rs = rsqrtf(var + 1e-6f);
        cf1s[n*64+lane]    = (v0-mu)*rs*lng[lane]    + lnb[lane];
        cf1s[n*64+lane+32] = (v1-mu)*rs*lng[lane+32] + lnb[lane+32];
    }
    __syncthreads();
    for (int it=0; it<128; it++){
        int idx = it*512 + tid;
        int s = idx>>6, c = idx&63;
        const float* w1p = g_w1 + b*5120 + s*5;
        float a = 0.f;
        #pragma unroll
        for (int n=0;n<5;n++) a = fmaf(w1p[n], cf1s[n*64+c], a);
        g_cf[b*65536 + idx] = a;
    }
}

// ====== Kernel Cm: fused QKV projection (tf32 mma), fp16 outputs ==========
// Q,K: [s][d~] (d perm16), Q pre-scaled by log2e/8. V: [d][s~] (s perm16).
__global__ __launch_bounds__(256) void kCm(
    const float* __restrict__ wq, const float* __restrict__ wk, const float* __restrict__ wv,
    const float* __restrict__ bq, const float* __restrict__ bk, const float* __restrict__ bv,
    __half* __restrict__ pq, __half* __restrict__ pk, __half* __restrict__ pv)
{
    extern __shared__ float smc[];
    float* Ast = smc;          // [128][68]
    float* Ws  = smc + 8704;   // [64][136]
    float* bs  = smc + 17408;  // [128]
    const int mt=blockIdx.x, nt=blockIdx.y;
    const int tid=threadIdx.x, w=tid>>5, lane=tid&31, gid=lane>>2, l4=lane&3;

    const float* Ap = g_cf + mt*128*64;
    #pragma unroll
    for (int i=0;i<8;i++){
        int idx=i*256+tid, row=idx>>4, c4=(idx&15)*4;
        *(float4*)(Ast + row*68 + c4) = *(const float4*)(Ap + row*64 + c4);
    }
    __syncthreads();

    unsigned af[8][4];
    const int r0 = w*16;
    #pragma unroll
    for (int kk=0;kk<8;kk++){
        af[kk][0]=__float_as_uint(Ast[(r0+gid  )*68 + kk*8   + l4]);
        af[kk][1]=__float_as_uint(Ast[(r0+gid+8)*68 + kk*8   + l4]);
        af[kk][2]=__float_as_uint(Ast[(r0+gid  )*68 + kk*8+4 + l4]);
        af[kk][3]=__float_as_uint(Ast[(r0+gid+8)*68 + kk*8+4 + l4]);
    }

    const int row_lo = mt*128 + r0 + gid;
    const int bidx = row_lo>>10, s_lo = row_lo&1023;
    const float QSC = 0.125f * 1.4426950408889634f;

    #pragma unroll
    for (int z=0; z<3; z++){
        const float* W  = (z==0)?wq:((z==1)?wk:wv);
        const float* Bp = (z==0)?bq:((z==1)?bk:bv);

        __syncthreads();   // prior z's readers done with Ws
        #pragma unroll
        for (int i=0;i<8;i++){
            int idx=i*256+tid, row=idx>>5, c4=(idx&31)*4;
            *(float4*)(Ws + row*136 + c4) = *(const float4*)(W + row*256 + nt*128 + c4);
        }
        if (tid<128) bs[tid] = Bp[nt*128+tid];
        __syncthreads();

        float c[16][4];
        #pragma unroll
        for (int j=0;j<16;j++){ c[j][0]=c[j][1]=c[j][2]=c[j][3]=0.f; }
        #pragma unroll
        for (int j=0;j<16;j++){
            #pragma unroll
            for (int kk=0;kk<8;kk++){
                unsigned b0=__float_as_uint(Ws[(kk*8+l4  )*136 + j*8+gid]);
                unsigned b1=__float_as_uint(Ws[(kk*8+l4+4)*136 + j*8+gid]);
                MMA_TF32(c[j][0],c[j][1],c[j][2],c[j][3],
                         af[kk][0],af[kk][1],af[kk][2],af[kk][3],b0,b1);
            }
        }
        const float sc = (z==0) ? QSC : 1.f;
        #pragma unroll
        for (int j=0;j<16;j++){
            int cl = j*8 + 2*l4;
            int col0 = nt*128 + cl;
            int h = col0>>6, d0 = col0&63, d1 = d0+1;
            float v00 = (c[j][0]+bs[cl  ])*sc;
            float v01 = (c[j][1]+bs[cl+1])*sc;
            float v10 = (c[j][2]+bs[cl  ])*sc;
            float v11 = (c[j][3]+bs[cl+1])*sc;
            if (z < 2){
                __half* op = ((z==0)?pq:pk) + (((bidx<<2)+h)<<16);
                int pd = perm16(d0);
                *(__half2*)(op + s_lo*64 + pd)     = __floats2half2_rn(v00, v01);
                *(__half2*)(op + (s_lo+8)*64 + pd) = __floats2half2_rn(v10, v11);
            } else {
                __half* op = pv + (((bidx<<2)+h)<<16);
                int ps0 = perm16(s_lo), ps8 = perm16(s_lo+8);
                op[d0*1024 + ps0] = __float2half_rn(v00);
                op[d1*1024 + ps0] = __float2half_rn(v01);
                op[d0*1024 + ps8] = __float2half_rn(v10);
                op[d1*1024 + ps8] = __float2half_rn(v11);
            }
        }
    }
}

// ========== Kernel D: fp16 mma flash attention, M=32/warp =================
// m16n8k16.f16: K=16/mma (2x tf32 rate), 2B elements (half LDS+GMEM bytes),
// perm16 layouts make every B-frag {b0,b1} one LDS.64. P feeds PV directly
// from S accum via f16x2 packs. smem 40,960B, 128 thr, 2 CTAs/SM.
__global__ __launch_bounds__(128, 2) void kD()
{
    extern __shared__ __half smh[];
    __half* KS0 = smh;            // [64][80]
    __half* VS0 = smh + 5120;     // [64][80] (V^T tile [d][s~])
    __half* KS1 = smh + 10240;
    __half* VS1 = smh + 15360;

    const int qt=blockIdx.x, h=blockIdx.y, b=blockIdx.z;
    const int tid=threadIdx.x, w=tid>>5, lane=tid&31;
    const int gid=lane>>2, l4=lane&3;
    const int base=((b*4+h)<<16);

    const __half* Kg = g_k + base;
    const __half* Vg = g_v + base;           // [64 d][1024 s~]
    const __half* Qg = g_q + base + qt*8192; // 128 x 64, pre-scaled

    // Q fragments straight from global (one-time; coalesced 8B/lane)
    unsigned qf[2][4][4];
    const int r0 = w*32;
    #pragma unroll
    for (int mt=0;mt<2;mt++){
        const int rb = r0 + mt*16;
        #pragma unroll
        for (int kc=0;kc<4;kc++){
            uint2 lo = *(const uint2*)(Qg + (rb+gid  )*64 + kc*16 + 4*l4);
            uint2 hi = *(const uint2*)(Qg + (rb+gid+8)*64 + kc*16 + 4*l4);
            qf[mt][kc][0]=lo.x; qf[mt][kc][1]=hi.x;
            qf[mt][kc][2]=lo.y; qf[mt][kc][3]=hi.y;
        }
    }

    // prefetch tiles 0,1 (K tile 8KB = 512 cp16; V same)
    #pragma unroll
    for (int i=0;i<4;i++){
        int idx=i*128+tid, row=idx>>3, c8=(idx&7)*8;
        cp16(KS0 + row*80 + c8, Kg + row*64 + c8);
        cp16(VS0 + row*80 + c8, Vg + row*1024 + c8);
    }
    CP_COMMIT;
    #pragma unroll
    for (int i=0;i<4;i++){
        int idx=i*128+tid, row=idx>>3, c8=(idx&7)*8;
        cp16(KS1 + row*80 + c8, Kg + 4096 + row*64 + c8);
        cp16(VS1 + row*80 + c8, Vg + 64 + row*1024 + c8);
    }
    CP_COMMIT;

    float o0[8][4], o1[8][4];
    #pragma unroll
    for (int n=0;n<8;n++){
        o0[n][0]=o0[n][1]=o0[n][2]=o0[n][3]=0.f;
        o1[n][0]=o1[n][1]=o1[n][2]=o1[n][3]=0.f;
    }
    float m_lo0=-1e30f, m_hi0=-1e30f, l_lo0=0.f, l_hi0=0.f;
    float m_lo1=-1e30f, m_hi1=-1e30f, l_lo1=0.f, l_hi1=0.f;

    for (int kt=0; kt<16; kt++){
        CP_WAIT1;
        __syncthreads();
        const __half* Ks_ = (kt&1) ? KS1 : KS0;
        const __half* Vs_ = (kt&1) ? VS1 : VS0;

        // ---- S = Q K^T : one LDS.64 per (j,kc) B-frag, reused both m-tiles
        float c0[8][4], c1[8][4];
        #pragma unroll
        for (int j=0;j<8;j++){
            c0[j][0]=c0[j][1]=c0[j][2]=c0[j][3]=0.f;
            c1[j][0]=c1[j][1]=c1[j][2]=c1[j][3]=0.f;
        }
        #pragma unroll
        for (int j=0;j<8;j++){
            #pragma unroll
            for (int kc=0;kc<4;kc++){
                uint2 bb = *(const uint2*)(Ks_ + (j*8+gid)*80 + kc*16 + 4*l4);
                MMA_F16(c0[j][0],c0[j][1],c0[j][2],c0[j][3],
                        qf[0][kc][0],qf[0][kc][1],qf[0][kc][2],qf[0][kc][3],bb.x,bb.y);
                MMA_F16(c1[j][0],c1[j][1],c1[j][2],c1[j][3],
                        qf[1][kc][0],qf[1][kc][1],qf[1][kc][2],qf[1][kc][3],bb.x,bb.y);
            }
        }

        // ---- online softmax (base-2), per m-tile ----
        {
            float mx_lo=-1e30f, mx_hi=-1e30f;
            #pragma unroll
            for (int j=0;j<8;j++){
                mx_lo = fmaxf(mx_lo, fmaxf(c0[j][0], c0[j][1]));
                mx_hi = fmaxf(mx_hi, fmaxf(c0[j][2], c0[j][3]));
            }
            mx_lo = fmaxf(mx_lo, __shfl_xor_sync(0xffffffffu, mx_lo, 1));
            mx_lo = fmaxf(mx_lo, __shfl_xor_sync(0xffffffffu, mx_lo, 2));
            mx_hi = fmaxf(mx_hi, __shfl_xor_sync(0xffffffffu, mx_hi, 1));
            mx_hi = fmaxf(mx_hi, __shfl_xor_sync(0xffffffffu, mx_hi, 2));
            float mn_lo = fmaxf(m_lo0, mx_lo), mn_hi = fmaxf(m_hi0, mx_hi);
            float al = fex2(m_lo0 - mn_lo), ah = fex2(m_hi0 - mn_hi);
            float s_lo=0.f, s_hi=0.f;
            #pragma unroll
            for (int j=0;j<8;j++){
                c0[j][0]=fex2(c0[j][0]-mn_lo); s_lo+=c0[j][0];
                c0[j][1]=fex2(c0[j][1]-mn_lo); s_lo+=c0[j][1];
                c0[j][2]=fex2(c0[j][2]-mn_hi); s_hi+=c0[j][2];
                c0[j][3]=fex2(c0[j][3]-mn_hi); s_hi+=c0[j][3];
            }
            s_lo += __shfl_xor_sync(0xffffffffu, s_lo, 1);
            s_lo += __shfl_xor_sync(0xffffffffu, s_lo, 2);
            s_hi += __shfl_xor_sync(0xffffffffu, s_hi, 1);
            s_hi += __shfl_xor_sync(0xffffffffu, s_hi, 2);
            l_lo0 = l_lo0*al + s_lo;  l_hi0 = l_hi0*ah + s_hi;
            m_lo0 = mn_lo;            m_hi0 = mn_hi;
            #pragma unroll
            for (int n=0;n<8;n++){
                o0[n][0]*=al; o0[n][1]*=al; o0[n][2]*=ah; o0[n][3]*=ah;
            }
        }
        {
            float mx_lo=-1e30f, mx_hi=-1e30f;
            #pragma unroll
            for (int j=0;j<8;j++){
                mx_lo = fmaxf(mx_lo, fmaxf(c1[j][0], c1[j][1]));
                mx_hi = fmaxf(mx_hi, fmaxf(c1[j][2], c1[j][3]));
            }
            mx_lo = fmaxf(mx_lo, __shfl_xor_sync(0xffffffffu, mx_lo, 1));
            mx_lo = fmaxf(mx_lo, __shfl_xor_sync(0xffffffffu, mx_lo, 2));
            mx_hi = fmaxf(mx_hi, __shfl_xor_sync(0xffffffffu, mx_hi, 1));
            mx_hi = fmaxf(mx_hi, __shfl_xor_sync(0xffffffffu, mx_hi, 2));
            float mn_lo = fmaxf(m_lo1, mx_lo), mn_hi = fmaxf(m_hi1, mx_hi);
            float al = fex2(m_lo1 - mn_lo), ah = fex2(m_hi1 - mn_hi);
            float s_lo=0.f, s_hi=0.f;
            #pragma unroll
            for (int j=0;j<8;j++){
                c1[j][0]=fex2(c1[j][0]-mn_lo); s_lo+=c1[j][0];
                c1[j][1]=fex2(c1[j][1]-mn_lo); s_lo+=c1[j][1];
                c1[j][2]=fex2(c1[j][2]-mn_hi); s_hi+=c1[j][2];
                c1[j][3]=fex2(c1[j][3]-mn_hi); s_hi+=c1[j][3];
            }
            s_lo += __shfl_xor_sync(0xffffffffu, s_lo, 1);
            s_lo += __shfl_xor_sync(0xffffffffu, s_lo, 2);
            s_hi += __shfl_xor_sync(0xffffffffu, s_hi, 1);
            s_hi += __shfl_xor_sync(0xffffffffu, s_hi, 2);
            l_lo1 = l_lo1*al + s_lo;  l_hi1 = l_hi1*ah + s_hi;
            m_lo1 = mn_lo;            m_hi1 = mn_hi;
            #pragma unroll
            for (int n=0;n<8;n++){
                o1[n][0]*=al; o1[n][1]*=al; o1[n][2]*=ah; o1[n][3]*=ah;
            }
        }

        // ---- O += P V : P packed from S accum (t-chunk = j tiles 2t,2t+1) --
        #pragma unroll
        for (int t=0;t<4;t++){
            unsigned a00 = pack_h2(c0[2*t  ][0], c0[2*t  ][1]);
            unsigned a01 = pack_h2(c0[2*t  ][2], c0[2*t  ][3]);
            unsigned a02 = pack_h2(c0[2*t+1][0], c0[2*t+1][1]);
            unsigned a03 = pack_h2(c0[2*t+1][2], c0[2*t+1][3]);
            unsigned a10 = pack_h2(c1[2*t  ][0], c1[2*t  ][1]);
            unsigned a11 = pack_h2(c1[2*t  ][2], c1[2*t  ][3]);
            unsigned a12 = pack_h2(c1[2*t+1][0], c1[2*t+1][1]);
            unsigned a13 = pack_h2(c1[2*t+1][2], c1[2*t+1][3]);
            #pragma unroll
            for (int n=0;n<8;n++){
                uint2 bb = *(const uint2*)(Vs_ + (n*8+gid)*80 + t*16 + 4*l4);
                MMA_F16(o0[n][0],o0[n][1],o0[n][2],o0[n][3],a00,a01,a02,a03,bb.x,bb.y);
                MMA_F16(o1[n][0],o1[n][1],o1[n][2],o1[n][3],a10,a11,a12,a13,bb.x,bb.y);
            }
        }

        __syncthreads();
        if (kt < 14){
            const __half* Kp = Kg + (kt+2)*4096;
            const __half* Vp = Vg + (kt+2)*64;
            __half* kd = (kt&1) ? KS1 : KS0;
            __half* vd = (kt&1) ? VS1 : VS0;
            #pragma unroll
            for (int i=0;i<4;i++){
                int idx=i*128+tid, row=idx>>3, c8=(idx&7)*8;
                cp16(kd + row*80 + c8, Kp + row*64 + c8);
                cp16(vd + row*80 + c8, Vp + row*1024 + c8);
            }
        }
        CP_COMMIT;
    }

    float* Op = g_o + base + qt*8192;
    {
        float il = 1.f/l_lo0, ih = 1.f/l_hi0;
        const int r_lo = r0 + gid, r_hi = r_lo + 8;
        #pragma unroll
        for (int n=0;n<8;n++){
            int col = n*8 + 2*l4;
            *(float2*)(Op + r_lo*64 + col) = make_float2(o0[n][0]*il, o0[n][1]*il);
            *(float2*)(Op + r_hi*64 + col) = make_float2(o0[n][2]*ih, o0[n][3]*ih);
        }
    }
    {
        float il = 1.f/l_lo1, ih = 1.f/l_hi1;
        const int r_lo = r0 + 16 + gid, r_hi = r_lo + 8;
        #pragma unroll
        for (int n=0;n<8;n++){
            int col = n*8 + 2*l4;
            *(float2*)(Op + r_lo*64 + col) = make_float2(o1[n][0]*il, o1[n][1]*il);
            *(float2*)(Op + r_hi*64 + col) = make_float2(o1[n][2]*ih, o1[n][3]*ih);
        }
    }
}

// ==== Kernel E2: tf32 mma out-proj + residual + LN + transpose ============
__global__ __launch_bounds__(256) void kE2(const float* __restrict__ fc,
                                           const float* __restrict__ fcb,
                                           const float* __restrict__ lng,
                                           const float* __restrict__ lnb,
                                           float* __restrict__ out)
{
    extern __shared__ float sme[];
    float* As = sme;           // [128][68] GEMM phase; Cs [128][69] epilogue
    float* Bs = sme + 8832;    // [64][68]
    float* Cs = sme;
    const int stile = blockIdx.x, b = blockIdx.y, tid = threadIdx.x;
    const int w=tid>>5, lane=tid&31, gid=lane>>2, l4=lane&3;
    const int r0 = w*16;
    const int s0 = stile*128;

    float c[8][4];
    #pragma unroll
    for (int j=0;j<8;j++){ c[j][0]=c[j][1]=c[j][2]=c[j][3]=0.f; }

    for (int h=0; h<4; h++){
        __syncthreads();
        const float* Ap = g_o + ((b*4+h)<<16) + s0*64;
        #pragma unroll
        for (int i=0;i<8;i++){
            int idx=i*256+tid, row=idx>>4, c4=(idx&15)*4;
            *(float4*)(As + row*68 + c4) = *(const float4*)(Ap + row*64 + c4);
        }
        #pragma unroll
        for (int i=0;i<4;i++){
            int idx=i*256+tid, row=idx>>4, c4=(idx&15)*4;
            *(float4*)(Bs + row*68 + c4) = *(const float4*)(fc + (h*64+row)*64 + c4);
        }
        __syncthreads();
        unsigned af[8][4];
        #pragma unroll
        for (int kk=0;kk<8;kk++){
            af[kk][0]=__float_as_uint(As[(r0+gid  )*68 + kk*8   + l4]);
            af[kk][1]=__float_as_uint(As[(r0+gid+8)*68 + kk*8   + l4]);
            af[kk][2]=__float_as_uint(As[(r0+gid  )*68 + kk*8+4 + l4]);
            af[kk][3]=__float_as_uint(As[(r0+gid+8)*68 + kk*8+4 + l4]);
        }
        #pragma unroll
        for (int j=0;j<8;j++){
            #pragma unroll
            for (int kk=0;kk<8;kk++){
                unsigned b0=__float_as_uint(Bs[(kk*8+l4  )*68 + j*8+gid]);
                unsigned b1=__float_as_uint(Bs[(kk*8+l4+4)*68 + j*8+gid]);
                MMA_TF32(c[j][0],c[j][1],c[j][2],c[j][3],
                         af[kk][0],af[kk][1],af[kk][2],af[kk][3],b0,b1);
            }
        }
    }
    __syncthreads();
    const int r_lo = r0 + gid, r_hi = r_lo + 8;
    #pragma unroll
    for (int j=0;j<8;j++){
        int col = j*8 + 2*l4;
        float b0 = fcb[col], b1 = fcb[col+1];
        Cs[r_lo*69+col  ] = c[j][0] + b0 + g_cf[b*65536 + (s0+r_lo)*64 + col  ];
        Cs[r_lo*69+col+1] = c[j][1] + b1 + g_cf[b*65536 + (s0+r_lo)*64 + col+1];
        Cs[r_hi*69+col  ] = c[j][2] + b0 + g_cf[b*65536 + (s0+r_hi)*64 + col  ];
        Cs[r_hi*69+col+1] = c[j][3] + b1 + g_cf[b*65536 + (s0+r_hi)*64 + col+1];
    }
    __syncthreads();
    for (int rr=0; rr<16; rr++){
        int r = w*16 + rr;
        float v0 = Cs[r*69+lane], v1 = Cs[r*69+lane+32];
        float sm = v0+v1, sq = v0*v0 + v1*v1;
        #pragma unroll
        for (int off=16; off; off>>=1){
            sm += __shfl_xor_sync(0xffffffffu, sm, off);
            sq += __shfl_xor_sync(0xffffffffu, sq, off);
        }
        float mu = sm*(1.f/64.f);
        float var = sq*(1.f/64.f) - mu*mu;
        float rstd = rsqrtf(var + 1e-6f);
        Cs[r*69+lane]    = (v0-mu)*rstd*lng[lane]    + lnb[lane];
        Cs[r*69+lane+32] = (v1-mu)*rstd*lng[lane+32] + lnb[lane+32];
    }
    __syncthreads();
    #pragma unroll
    for (int i=0;i<32;i++){
        int idx = i*256 + tid;
        int cc = idx>>7, sl = idx&127;
        out[(((b<<6)+cc)<<10) + s0 + sl] = Cs[sl*69+cc];
    }
}

// ============================== launcher ===================================
extern "C" void kernel_launch(void* const* d_in, const int* in_sizes, int n_in,
                              void* d_out, int out_size)
{
    const float* x      = (const float*)d_in[0];
    const float* memory = (const float*)d_in[1];
    const float* wb_w   = (const float*)d_in[2];
    const float* wb_b   = (const float*)d_in[3];
    const float* a1_wq  = (const float*)d_in[4];
    const float* a1_bq  = (const float*)d_in[5];
    const float* a1_wk  = (const float*)d_in[6];
    const float* a1_bk  = (const float*)d_in[7];
    const float* a1_wv  = (const float*)d_in[8];
    const float* a1_bv  = (const float*)d_in[9];
    const float* a1_fc  = (const float*)d_in[10];
    const float* a1_fcb = (const float*)d_in[11];
    const float* a1_lng = (const float*)d_in[12];
    const float* a1_lnb = (const float*)d_in[13];
    const float* a2_wq  = (const float*)d_in[14];
    const float* a2_bq  = (const float*)d_in[15];
    const float* a2_wk  = (const float*)d_in[16];
    const float* a2_bk  = (const float*)d_in[17];
    const float* a2_wv  = (const float*)d_in[18];
    const float* a2_bv  = (const float*)d_in[19];
    const float* a2_fc  = (const float*)d_in[20];
    const float* a2_fcb = (const float*)d_in[21];
    const float* a2_lng = (const float*)d_in[22];
    const float* a2_lnb = (const float*)d_in[23];
    float* out = (float*)d_out;

    __half *pq=0, *pk=0, *pv=0;
    cudaGetSymbolAddress((void**)&pq, g_q);
    cudaGetSymbolAddress((void**)&pk, g_k);
    cudaGetSymbolAddress((void**)&pv, g_v);

    const int kcm_smem = 17536*4;          // 70144 B
    const int kd_smem  = 20480*2;          // 40960 B -> 2 CTAs/SM (reg-capped)
    const int ke_smem  = (8832+4352)*4;    // 52736 B
    cudaFuncSetAttribute(kCm, cudaFuncAttributeMaxDynamicSharedMemorySize, kcm_smem);
    cudaFuncSetAttribute(kD,  cudaFuncAttributeMaxDynamicSharedMemorySize, kd_smem);
    cudaFuncSetAttribute(kE2, cudaFuncAttributeMaxDynamicSharedMemorySize, ke_smem);

    kA<<<NB, 1024>>>(x, wb_w, wb_b);
    dim3 gP(16, NB);
    kP<<<gP, 256>>>(x);
    kB<<<NB, 512>>>(memory, a1_wq, a1_bq, a1_wk, a1_bk, a1_wv, a1_bv,
                    a1_fc, a1_fcb, a1_lng, a1_lnb);
    dim3 gC(128, 2);
    kCm<<<gC, 256, kcm_smem>>>(a2_wq, a2_wk, a2_wv, a2_bq, a2_bk, a2_bv, pq, pk, pv);
    dim3 gD(8, 4, NB);
    kD<<<gD, 128, kd_smem>>>();
    dim3 gE(8, NB);
    kE2<<<gE, 256, ke_smem>>>(a2_fc, a2_fcb, a2_lng, a2_lnb, out);
}

// round 12
// speedup vs baseline: 2.1823x; 1.0969x over previous
#include <cuda_runtime.h>
#include <cuda_fp16.h>
#include <math.h>

#define NB   16
#define SEQ  1024
#define CH   64
#define NC   5
#define MD   96

// ---------------- scratch (device globals; no allocation) ----------------
__device__ float g_w1[NB*SEQ*NC];
__device__ float g_w2[NB*NC*SEQ];
__device__ float g_cf[NB*SEQ*CH];
__device__ float g_pool[NB*16*NC*64];
// fp16 Q/K/V/O. Q,K,O: [b][h][s][d~] with d perm16'd, Q pre-scaled by log2e/8.
// V: [b][h][d][s~] transposed with s perm16'd.
__device__ __align__(16) __half g_q[NB*4*SEQ*64];
__device__ __align__(16) __half g_k[NB*4*SEQ*64];
__device__ __align__(16) __half g_v[NB*4*SEQ*64];
__device__ __align__(16) __half g_o[NB*4*SEQ*64];

// ---------------- helpers ----------------
__device__ __forceinline__ float fex2(float x){
    float r; asm("ex2.approx.ftz.f32 %0, %1;" : "=f"(r) : "f"(x));
    return r;
}
__device__ __forceinline__ unsigned pack_h2(float lo, float hi){
    unsigned r; asm("cvt.rn.f16x2.f32 %0, %1, %2;" : "=r"(r) : "f"(hi), "f"(lo));
    return r;
}
// within each 16-group: pair q -> slot 2*(q&3)+(q>>2); pairs stay adjacent.
__device__ __forceinline__ int perm16(int k){
    int g = k & ~15, q = (k & 15) >> 1, odd = k & 1;
    int slot = ((q & 3) << 1) | (q >> 2);
    return g | (slot << 1) | odd;
}
__device__ __forceinline__ void cp16(void* dst, const void* src){
    unsigned d = (unsigned)__cvta_generic_to_shared(dst);
    asm volatile("cp.async.cg.shared.global [%0], [%1], 16;" :: "r"(d), "l"(src));
}
#define CP_COMMIT asm volatile("cp.async.commit_group;")
#define CP_WAIT1  asm volatile("cp.async.wait_group 1;")

#define MMA_TF32(c0,c1,c2,c3,a0,a1,a2,a3,b0,b1)                               \
  asm volatile("mma.sync.aligned.m16n8k8.row.col.f32.tf32.tf32.f32 "          \
    "{%0,%1,%2,%3}, {%4,%5,%6,%7}, {%8,%9}, {%0,%1,%2,%3};"                   \
    : "+f"(c0),"+f"(c1),"+f"(c2),"+f"(c3)                                     \
    : "r"(a0),"r"(a1),"r"(a2),"r"(a3),"r"(b0),"r"(b1))

#define MMA_F16(c0,c1,c2,c3,a0,a1,a2,a3,b0,b1)                                \
  asm volatile("mma.sync.aligned.m16n8k16.row.col.f32.f16.f16.f32 "           \
    "{%0,%1,%2,%3}, {%4,%5,%6,%7}, {%8,%9}, {%0,%1,%2,%3};"                   \
    : "+f"(c0),"+f"(c1),"+f"(c2),"+f"(c3)                                     \
    : "r"(a0),"r"(a1),"r"(a2),"r"(a3),"r"(b0),"r"(b1))

// ================= Kernel A: weight = xt@wb_w, both softmaxes =============
__global__ __launch_bounds__(1024) void kA(const float* __restrict__ x,
                                           const float* __restrict__ wbw,
                                           const float* __restrict__ wbb)
{
    const int b = blockIdx.x, s = threadIdx.x;
    __shared__ float ws[CH*NC];
    __shared__ float red[32*NC];
    __shared__ float Mx[NC], Sx[NC];
    if (s < CH*NC) ws[s] = wbw[s];
    __syncthreads();

    const float* xb = x + b*(CH*SEQ) + s;
    float w[NC];
    #pragma unroll
    for (int n=0;n<NC;n++) w[n] = wbb[n];
    #pragma unroll 8
    for (int c=0;c<CH;c++){
        float xv = xb[c<<10];
        #pragma unroll
        for (int n=0;n<NC;n++) w[n] = fmaf(xv, ws[c*NC+n], w[n]);
    }

    {
        float mx = w[0];
        #pragma unroll
        for (int n=1;n<NC;n++) mx = fmaxf(mx, w[n]);
        float e[NC], ssum = 0.f;
        #pragma unroll
        for (int n=0;n<NC;n++){ e[n] = __expf(w[n]-mx); ssum += e[n]; }
        float inv = 1.f/ssum;
        float* w1p = g_w1 + b*(SEQ*NC) + s*NC;
        #pragma unroll
        for (int n=0;n<NC;n++) w1p[n] = e[n]*inv;
    }

    const int lane = s & 31, wid = s >> 5;
    float r5[NC];
    #pragma unroll
    for (int n=0;n<NC;n++) r5[n] = w[n];
    #pragma unroll
    for (int off=16; off; off>>=1)
        #pragma unroll
        for (int n=0;n<NC;n++) r5[n] = fmaxf(r5[n], __shfl_xor_sync(0xffffffffu, r5[n], off));
    if (lane==0){
        #pragma unroll
        for (int n=0;n<NC;n++) red[wid*NC+n] = r5[n];
    }
    __syncthreads();
    if (wid==0){
        #pragma unroll
        for (int n=0;n<NC;n++) r5[n] = red[lane*NC+n];
        #pragma unroll
        for (int off=16; off; off>>=1)
            #pragma unroll
            for (int n=0;n<NC;n++) r5[n] = fmaxf(r5[n], __shfl_xor_sync(0xffffffffu, r5[n], off));
        if (lane==0){
            #pragma unroll
            for (int n=0;n<NC;n++) Mx[n] = r5[n];
        }
    }
    __syncthreads();
    float e2[NC];
    #pragma unroll
    for (int n=0;n<NC;n++){ e2[n] = __expf(w[n]-Mx[n]); r5[n] = e2[n]; }
    #pragma unroll
    for (int off=16; off; off>>=1)
        #pragma unroll
        for (int n=0;n<NC;n++) r5[n] += __shfl_xor_sync(0xffffffffu, r5[n], off);
    if (lane==0){
        #pragma unroll
        for (int n=0;n<NC;n++) red[wid*NC+n] = r5[n];
    }
    __syncthreads();
    if (wid==0){
        #pragma unroll
        for (int n=0;n<NC;n++) r5[n] = red[lane*NC+n];
        #pragma unroll
        for (int off=16; off; off>>=1)
            #pragma unroll
            for (int n=0;n<NC;n++) r5[n] += __shfl_xor_sync(0xffffffffu, r5[n], off);
        if (lane==0){
            #pragma unroll
            for (int n=0;n<NC;n++) Sx[n] = r5[n];
        }
    }
    __syncthreads();
    float* w2p = g_w2 + b*(NC*SEQ) + s;
    #pragma unroll
    for (int n=0;n<NC;n++) w2p[n<<10] = e2[n] / Sx[n];
}

// ====== Kernel P: parallel class pooling partials =========================
__global__ __launch_bounds__(256) void kP(const float* __restrict__ x)
{
    const int st = blockIdx.x, b = blockIdx.y, tid = threadIdx.x;
    __shared__ float xs[64*65];
    __shared__ float w2s[NC*64];
    const int s0 = st*64;
    #pragma unroll
    for (int i=0;i<16;i++){
        int idx = i*256 + tid;
        int c = idx>>6, sl = idx&63;
        xs[c*65+sl] = x[b*65536 + (c<<10) + s0 + sl];
    }
    for (int idx=tid; idx<NC*64; idx+=256)
        w2s[idx] = g_w2[b*5120 + ((idx>>6)<<10) + s0 + (idx&63)];
    __syncthreads();
    for (int idx=tid; idx<NC*64; idx+=256){
        const int n = idx>>6, c = idx&63;
        float a = 0.f;
        #pragma unroll 8
        for (int sl=0; sl<64; sl++) a = fmaf(w2s[n*64+sl], xs[c*65+sl], a);
        g_pool[(b*16+st)*320 + idx] = a;
    }
}

// ====== Kernel B: reduce pooling, MHA1 (5 tokens vs memory), redistribute ==
__global__ __launch_bounds__(512) void kB(
    const float* __restrict__ memory,
    const float* __restrict__ wq, const float* __restrict__ bq,
    const float* __restrict__ wk, const float* __restrict__ bk,
    const float* __restrict__ wv, const float* __restrict__ bv,
    const float* __restrict__ fc, const float* __restrict__ fcb,
    const float* __restrict__ lng, const float* __restrict__ lnb)
{
    const int b = blockIdx.x, tid = threadIdx.x;
    __shared__ float cf1s[NC*64];
    __shared__ float mems[NC*MD];
    __shared__ float qh[NC*MD], kh[NC*MD], vh[NC*64];
    __shared__ float Ssm[NC*NC];
    __shared__ float osm[NC*64];
    __shared__ float projs[NC*64];

    if (tid < 320){
        float acc = 0.f;
        #pragma unroll
        for (int st=0; st<16; st++) acc += g_pool[(b*16+st)*320 + tid];
        cf1s[tid] = acc;
    }
    if (tid < NC*MD) mems[tid] = memory[tid];
    __syncthreads();

    if (tid < 480){
        const int n = tid/96, j = tid - n*96;
        float q = bq[j];
        #pragma unroll
        for (int d=0; d<64; d++) q = fmaf(cf1s[n*64+d], wq[d*96+j], q);
        qh[tid] = q * 0.102062072615966f;
        float kk = bk[j];
        #pragma unroll
        for (int d=0; d<96; d++) kk = fmaf(mems[n*96+d], wk[d*96+j], kk);
        kh[tid] = kk;
    }
    if (tid < 320){
        const int n = tid>>6, c = tid&63;
        float vv = bv[c];
        #pragma unroll
        for (int d=0; d<96; d++) vv = fmaf(mems[n*96+d], wv[d*64+c], vv);
        vh[tid] = vv;
    }
    __syncthreads();

    if (tid < 25){
        const int i = tid/5, j = tid - (tid/5)*5;
        float sv = 0.f;
        #pragma unroll
        for (int d=0; d<96; d++) sv = fmaf(qh[i*96+d], kh[j*96+d], sv);
        Ssm[tid] = sv;
    }
    __syncthreads();
    if (tid < 5){
        float m = Ssm[tid*5];
        #pragma unroll
        for (int j=1;j<5;j++) m = fmaxf(m, Ssm[tid*5+j]);
        float p[5], sum = 0.f;
        #pragma unroll
        for (int j=0;j<5;j++){ p[j] = __expf(Ssm[tid*5+j]-m); sum += p[j]; }
        float inv = 1.f/sum;
        #pragma unroll
        for (int j=0;j<5;j++) Ssm[tid*5+j] = p[j]*inv;
    }
    __syncthreads();
    if (tid < 320){
        const int n = tid>>6, c = tid&63;
        float o = 0.f;
        #pragma unroll
        for (int j=0;j<5;j++) o = fmaf(Ssm[n*5+j], vh[j*64+c], o);
        osm[tid] = o;
    }
    __syncthreads();
    if (tid < 320){
        const int n = tid>>6, c = tid&63;
        float p = fcb[c] + cf1s[tid];
        #pragma unroll
        for (int k=0;k<64;k++) p = fmaf(osm[n*64+k], fc[k*64+c], p);
        projs[tid] = p;
    }
    __syncthreads();
    if (tid < 160){
        const int n = tid>>5, lane = tid&31;
        float v0 = projs[n*64+lane], v1 = projs[n*64+lane+32];
        float sm = v0+v1, sq = v0*v0 + v1*v1;
        #pragma unroll
        for (int off=16; off; off>>=1){
            sm += __shfl_xor_sync(0xffffffffu, sm, off);
            sq += __shfl_xor_sync(0xffffffffu, sq, off);
        }
        float mu = sm*(1.f/64.f);
        float var = sq*(1.f/64.f) - mu*mu;
        float rs = rsqrtf(var + 1e-6f);
        cf1s[n*64+lane]    = (v0-mu)*rs*lng[lane]    + lnb[lane];
        cf1s[n*64+lane+32] = (v1-mu)*rs*lng[lane+32] + lnb[lane+32];
    }
    __syncthreads();
    for (int it=0; it<128; it++){
        int idx = it*512 + tid;
        int s = idx>>6, c = idx&63;
        const float* w1p = g_w1 + b*5120 + s*5;
        float a = 0.f;
        #pragma unroll
        for (int n=0;n<5;n++) a = fmaf(w1p[n], cf1s[n*64+c], a);
        g_cf[b*65536 + idx] = a;
    }
}

// ====== Kernel Cm: fused QKV projection (tf32 mma), fp16 outputs ==========
__global__ __launch_bounds__(256) void kCm(
    const float* __restrict__ wq, const float* __restrict__ wk, const float* __restrict__ wv,
    const float* __restrict__ bq, const float* __restrict__ bk, const float* __restrict__ bv,
    __half* __restrict__ pq, __half* __restrict__ pk, __half* __restrict__ pv)
{
    extern __shared__ float smc[];
    float* Ast = smc;          // [128][68]
    float* Ws  = smc + 8704;   // [64][136]
    float* bs  = smc + 17408;  // [128]
    const int mt=blockIdx.x, nt=blockIdx.y;
    const int tid=threadIdx.x, w=tid>>5, lane=tid&31, gid=lane>>2, l4=lane&3;

    const float* Ap = g_cf + mt*128*64;
    #pragma unroll
    for (int i=0;i<8;i++){
        int idx=i*256+tid, row=idx>>4, c4=(idx&15)*4;
        *(float4*)(Ast + row*68 + c4) = *(const float4*)(Ap + row*64 + c4);
    }
    __syncthreads();

    unsigned af[8][4];
    const int r0 = w*16;
    #pragma unroll
    for (int kk=0;kk<8;kk++){
        af[kk][0]=__float_as_uint(Ast[(r0+gid  )*68 + kk*8   + l4]);
        af[kk][1]=__float_as_uint(Ast[(r0+gid+8)*68 + kk*8   + l4]);
        af[kk][2]=__float_as_uint(Ast[(r0+gid  )*68 + kk*8+4 + l4]);
        af[kk][3]=__float_as_uint(Ast[(r0+gid+8)*68 + kk*8+4 + l4]);
    }

    const int row_lo = mt*128 + r0 + gid;
    const int bidx = row_lo>>10, s_lo = row_lo&1023;
    const float QSC = 0.125f * 1.4426950408889634f;

    #pragma unroll
    for (int z=0; z<3; z++){
        const float* W  = (z==0)?wq:((z==1)?wk:wv);
        const float* Bp = (z==0)?bq:((z==1)?bk:bv);

        __syncthreads();
        #pragma unroll
        for (int i=0;i<8;i++){
            int idx=i*256+tid, row=idx>>5, c4=(idx&31)*4;
            *(float4*)(Ws + row*136 + c4) = *(const float4*)(W + row*256 + nt*128 + c4);
        }
        if (tid<128) bs[tid] = Bp[nt*128+tid];
        __syncthreads();

        float c[16][4];
        #pragma unroll
        for (int j=0;j<16;j++){ c[j][0]=c[j][1]=c[j][2]=c[j][3]=0.f; }
        #pragma unroll
        for (int j=0;j<16;j++){
            #pragma unroll
            for (int kk=0;kk<8;kk++){
                unsigned b0=__float_as_uint(Ws[(kk*8+l4  )*136 + j*8+gid]);
                unsigned b1=__float_as_uint(Ws[(kk*8+l4+4)*136 + j*8+gid]);
                MMA_TF32(c[j][0],c[j][1],c[j][2],c[j][3],
                         af[kk][0],af[kk][1],af[kk][2],af[kk][3],b0,b1);
            }
        }
        const float sc = (z==0) ? QSC : 1.f;
        #pragma unroll
        for (int j=0;j<16;j++){
            int cl = j*8 + 2*l4;
            int col0 = nt*128 + cl;
            int h = col0>>6, d0 = col0&63, d1 = d0+1;
            float v00 = (c[j][0]+bs[cl  ])*sc;
            float v01 = (c[j][1]+bs[cl+1])*sc;
            float v10 = (c[j][2]+bs[cl  ])*sc;
            float v11 = (c[j][3]+bs[cl+1])*sc;
            if (z < 2){
                __half* op = ((z==0)?pq:pk) + (((bidx<<2)+h)<<16);
                int pd = perm16(d0);
                *(__half2*)(op + s_lo*64 + pd)     = __floats2half2_rn(v00, v01);
                *(__half2*)(op + (s_lo+8)*64 + pd) = __floats2half2_rn(v10, v11);
            } else {
                __half* op = pv + (((bidx<<2)+h)<<16);
                int ps0 = perm16(s_lo), ps8 = perm16(s_lo+8);
                op[d0*1024 + ps0] = __float2half_rn(v00);
                op[d1*1024 + ps0] = __float2half_rn(v01);
                op[d0*1024 + ps8] = __float2half_rn(v10);
                op[d1*1024 + ps8] = __float2half_rn(v11);
            }
        }
    }
}

// ========== Kernel D: fp16 mma flash attention, M=32/warp =================
// O written fp16 with perm16 d layout (feeds kE2 A-fragments directly).
__global__ __launch_bounds__(128, 2) void kD()
{
    extern __shared__ __half smh[];
    __half* KS0 = smh;            // [64][80]
    __half* VS0 = smh + 5120;     // [64][80] (V^T tile [d][s~])
    __half* KS1 = smh + 10240;
    __half* VS1 = smh + 15360;

    const int qt=blockIdx.x, h=blockIdx.y, b=blockIdx.z;
    const int tid=threadIdx.x, w=tid>>5, lane=tid&31;
    const int gid=lane>>2, l4=lane&3;
    const int base=((b*4+h)<<16);

    const __half* Kg = g_k + base;
    const __half* Vg = g_v + base;           // [64 d][1024 s~]
    const __half* Qg = g_q + base + qt*8192; // 128 x 64, pre-scaled

    unsigned qf[2][4][4];
    const int r0 = w*32;
    #pragma unroll
    for (int mt=0;mt<2;mt++){
        const int rb = r0 + mt*16;
        #pragma unroll
        for (int kc=0;kc<4;kc++){
            uint2 lo = *(const uint2*)(Qg + (rb+gid  )*64 + kc*16 + 4*l4);
            uint2 hi = *(const uint2*)(Qg + (rb+gid+8)*64 + kc*16 + 4*l4);
            qf[mt][kc][0]=lo.x; qf[mt][kc][1]=hi.x;
            qf[mt][kc][2]=lo.y; qf[mt][kc][3]=hi.y;
        }
    }

    #pragma unroll
    for (int i=0;i<4;i++){
        int idx=i*128+tid, row=idx>>3, c8=(idx&7)*8;
        cp16(KS0 + row*80 + c8, Kg + row*64 + c8);
        cp16(VS0 + row*80 + c8, Vg + row*1024 + c8);
    }
    CP_COMMIT;
    #pragma unroll
    for (int i=0;i<4;i++){
        int idx=i*128+tid, row=idx>>3, c8=(idx&7)*8;
        cp16(KS1 + row*80 + c8, Kg + 4096 + row*64 + c8);
        cp16(VS1 + row*80 + c8, Vg + 64 + row*1024 + c8);
    }
    CP_COMMIT;

    float o0[8][4], o1[8][4];
    #pragma unroll
    for (int n=0;n<8;n++){
        o0[n][0]=o0[n][1]=o0[n][2]=o0[n][3]=0.f;
        o1[n][0]=o1[n][1]=o1[n][2]=o1[n][3]=0.f;
    }
    float m_lo0=-1e30f, m_hi0=-1e30f, l_lo0=0.f, l_hi0=0.f;
    float m_lo1=-1e30f, m_hi1=-1e30f, l_lo1=0.f, l_hi1=0.f;

    for (int kt=0; kt<16; kt++){
        CP_WAIT1;
        __syncthreads();
        const __half* Ks_ = (kt&1) ? KS1 : KS0;
        const __half* Vs_ = (kt&1) ? VS1 : VS0;

        float c0[8][4], c1[8][4];
        #pragma unroll
        for (int j=0;j<8;j++){
            c0[j][0]=c0[j][1]=c0[j][2]=c0[j][3]=0.f;
            c1[j][0]=c1[j][1]=c1[j][2]=c1[j][3]=0.f;
        }
        #pragma unroll
        for (int j=0;j<8;j++){
            #pragma unroll
            for (int kc=0;kc<4;kc++){
                uint2 bb = *(const uint2*)(Ks_ + (j*8+gid)*80 + kc*16 + 4*l4);
                MMA_F16(c0[j][0],c0[j][1],c0[j][2],c0[j][3],
                        qf[0][kc][0],qf[0][kc][1],qf[0][kc][2],qf[0][kc][3],bb.x,bb.y);
                MMA_F16(c1[j][0],c1[j][1],c1[j][2],c1[j][3],
                        qf[1][kc][0],qf[1][kc][1],qf[1][kc][2],qf[1][kc][3],bb.x,bb.y);
            }
        }

        {
            float mx_lo=-1e30f, mx_hi=-1e30f;
            #pragma unroll
            for (int j=0;j<8;j++){
                mx_lo = fmaxf(mx_lo, fmaxf(c0[j][0], c0[j][1]));
                mx_hi = fmaxf(mx_hi, fmaxf(c0[j][2], c0[j][3]));
            }
            mx_lo = fmaxf(mx_lo, __shfl_xor_sync(0xffffffffu, mx_lo, 1));
            mx_lo = fmaxf(mx_lo, __shfl_xor_sync(0xffffffffu, mx_lo, 2));
            mx_hi = fmaxf(mx_hi, __shfl_xor_sync(0xffffffffu, mx_hi, 1));
            mx_hi = fmaxf(mx_hi, __shfl_xor_sync(0xffffffffu, mx_hi, 2));
            float mn_lo = fmaxf(m_lo0, mx_lo), mn_hi = fmaxf(m_hi0, mx_hi);
            float al = fex2(m_lo0 - mn_lo), ah = fex2(m_hi0 - mn_hi);
            float s_lo=0.f, s_hi=0.f;
            #pragma unroll
            for (int j=0;j<8;j++){
                c0[j][0]=fex2(c0[j][0]-mn_lo); s_lo+=c0[j][0];
                c0[j][1]=fex2(c0[j][1]-mn_lo); s_lo+=c0[j][1];
                c0[j][2]=fex2(c0[j][2]-mn_hi); s_hi+=c0[j][2];
                c0[j][3]=fex2(c0[j][3]-mn_hi); s_hi+=c0[j][3];
            }
            s_lo += __shfl_xor_sync(0xffffffffu, s_lo, 1);
            s_lo += __shfl_xor_sync(0xffffffffu, s_lo, 2);
            s_hi += __shfl_xor_sync(0xffffffffu, s_hi, 1);
            s_hi += __shfl_xor_sync(0xffffffffu, s_hi, 2);
            l_lo0 = l_lo0*al + s_lo;  l_hi0 = l_hi0*ah + s_hi;
            m_lo0 = mn_lo;            m_hi0 = mn_hi;
            #pragma unroll
            for (int n=0;n<8;n++){
                o0[n][0]*=al; o0[n][1]*=al; o0[n][2]*=ah; o0[n][3]*=ah;
            }
        }
        {
            float mx_lo=-1e30f, mx_hi=-1e30f;
            #pragma unroll
            for (int j=0;j<8;j++){
                mx_lo = fmaxf(mx_lo, fmaxf(c1[j][0], c1[j][1]));
                mx_hi = fmaxf(mx_hi, fmaxf(c1[j][2], c1[j][3]));
            }
            mx_lo = fmaxf(mx_lo, __shfl_xor_sync(0xffffffffu, mx_lo, 1));
            mx_lo = fmaxf(mx_lo, __shfl_xor_sync(0xffffffffu, mx_lo, 2));
            mx_hi = fmaxf(mx_hi, __shfl_xor_sync(0xffffffffu, mx_hi, 1));
            mx_hi = fmaxf(mx_hi, __shfl_xor_sync(0xffffffffu, mx_hi, 2));
            float mn_lo = fmaxf(m_lo1, mx_lo), mn_hi = fmaxf(m_hi1, mx_hi);
            float al = fex2(m_lo1 - mn_lo), ah = fex2(m_hi1 - mn_hi);
            float s_lo=0.f, s_hi=0.f;
            #pragma unroll
            for (int j=0;j<8;j++){
                c1[j][0]=fex2(c1[j][0]-mn_lo); s_lo+=c1[j][0];
                c1[j][1]=fex2(c1[j][1]-mn_lo); s_lo+=c1[j][1];
                c1[j][2]=fex2(c1[j][2]-mn_hi); s_hi+=c1[j][2];
                c1[j][3]=fex2(c1[j][3]-mn_hi); s_hi+=c1[j][3];
            }
            s_lo += __shfl_xor_sync(0xffffffffu, s_lo, 1);
            s_lo += __shfl_xor_sync(0xffffffffu, s_lo, 2);
            s_hi += __shfl_xor_sync(0xffffffffu, s_hi, 1);
            s_hi += __shfl_xor_sync(0xffffffffu, s_hi, 2);
            l_lo1 = l_lo1*al + s_lo;  l_hi1 = l_hi1*ah + s_hi;
            m_lo1 = mn_lo;            m_hi1 = mn_hi;
            #pragma unroll
            for (int n=0;n<8;n++){
                o1[n][0]*=al; o1[n][1]*=al; o1[n][2]*=ah; o1[n][3]*=ah;
            }
        }

        #pragma unroll
        for (int t=0;t<4;t++){
            unsigned a00 = pack_h2(c0[2*t  ][0], c0[2*t  ][1]);
            unsigned a01 = pack_h2(c0[2*t  ][2], c0[2*t  ][3]);
            unsigned a02 = pack_h2(c0[2*t+1][0], c0[2*t+1][1]);
            unsigned a03 = pack_h2(c0[2*t+1][2], c0[2*t+1][3]);
            unsigned a10 = pack_h2(c1[2*t  ][0], c1[2*t  ][1]);
            unsigned a11 = pack_h2(c1[2*t  ][2], c1[2*t  ][3]);
            unsigned a12 = pack_h2(c1[2*t+1][0], c1[2*t+1][1]);
            unsigned a13 = pack_h2(c1[2*t+1][2], c1[2*t+1][3]);
            #pragma unroll
            for (int n=0;n<8;n++){
                uint2 bb = *(const uint2*)(Vs_ + (n*8+gid)*80 + t*16 + 4*l4);
                MMA_F16(o0[n][0],o0[n][1],o0[n][2],o0[n][3],a00,a01,a02,a03,bb.x,bb.y);
                MMA_F16(o1[n][0],o1[n][1],o1[n][2],o1[n][3],a10,a11,a12,a13,bb.x,bb.y);
            }
        }

        __syncthreads();
        if (kt < 14){
            const __half* Kp = Kg + (kt+2)*4096;
            const __half* Vp = Vg + (kt+2)*64;
            __half* kd = (kt&1) ? KS1 : KS0;
            __half* vd = (kt&1) ? VS1 : VS0;
            #pragma unroll
            for (int i=0;i<4;i++){
                int idx=i*128+tid, row=idx>>3, c8=(idx&7)*8;
                cp16(kd + row*80 + c8, Kp + row*64 + c8);
                cp16(vd + row*80 + c8, Vp + row*1024 + c8);
            }
        }
        CP_COMMIT;
    }

    // epilogue: write O fp16 in perm16-d layout (same layout as g_q)
    __half* Op = g_o + base + qt*8192;
    {
        float il = 1.f/l_lo0, ih = 1.f/l_hi0;
        const int r_lo = r0 + gid, r_hi = r_lo + 8;
        #pragma unroll
        for (int n=0;n<8;n++){
            int pd = perm16(n*8 + 2*l4);
            *(__half2*)(Op + r_lo*64 + pd) = __floats2half2_rn(o0[n][0]*il, o0[n][1]*il);
            *(__half2*)(Op + r_hi*64 + pd) = __floats2half2_rn(o0[n][2]*ih, o0[n][3]*ih);
        }
    }
    {
        float il = 1.f/l_lo1, ih = 1.f/l_hi1;
        const int r_lo = r0 + 16 + gid, r_hi = r_lo + 8;
        #pragma unroll
        for (int n=0;n<8;n++){
            int pd = perm16(n*8 + 2*l4);
            *(__half2*)(Op + r_lo*64 + pd) = __floats2half2_rn(o1[n][0]*il, o1[n][1]*il);
            *(__half2*)(Op + r_hi*64 + pd) = __floats2half2_rn(o1[n][2]*ih, o1[n][3]*ih);
        }
    }
}

// ==== Kernel E3: fp16 mma out-proj + residual + LN + transpose ============
// A (g_o fp16, perm16 d) fragments straight from global; B (fc) converted to
// fp16 perm16 [n][k~] smem tiles (the proven Ks pattern). fp32 epilogue.
__global__ __launch_bounds__(256) void kE3(const float* __restrict__ fc,
                                           const float* __restrict__ fcb,
                                           const float* __restrict__ lng,
                                           const float* __restrict__ lnb,
                                           float* __restrict__ out)
{
    extern __shared__ float sme[];
    float*  Cs = sme;              // [128][69] epilogue
    __half* Bs = (__half*)sme;     // [64 n][80 k~] GEMM phase (alias)
    const int stile = blockIdx.x, b = blockIdx.y, tid = threadIdx.x;
    const int w=tid>>5, lane=tid&31, gid=lane>>2, l4=lane&3;
    const int r0 = w*16;
    const int s0 = stile*128;

    float c[8][4];
    #pragma unroll
    for (int j=0;j<8;j++){ c[j][0]=c[j][1]=c[j][2]=c[j][3]=0.f; }

    for (int h=0; h<4; h++){
        __syncthreads();   // prior phase readers done with Bs
        // stage B: fc[h*64+k][n] -> Bs[n*80 + perm16(k)]  (fp32 -> fp16)
        #pragma unroll
        for (int i=0;i<4;i++){
            int idx = i*256 + tid;
            int k = idx>>4, n4 = (idx&15)*4;
            float4 v = *(const float4*)(fc + (h*64+k)*64 + n4);
            int pk = perm16(k);
            Bs[(n4  )*80 + pk] = __float2half_rn(v.x);
            Bs[(n4+1)*80 + pk] = __float2half_rn(v.y);
            Bs[(n4+2)*80 + pk] = __float2half_rn(v.z);
            Bs[(n4+3)*80 + pk] = __float2half_rn(v.w);
        }
        __syncthreads();

        // A fragments from global (g_o perm16 layout == g_q pattern)
        const __half* Ap = g_o + ((b*4+h)<<16) + s0*64;
        unsigned af[4][4];
        #pragma unroll
        for (int kc=0;kc<4;kc++){
            uint2 lo = *(const uint2*)(Ap + (r0+gid  )*64 + kc*16 + 4*l4);
            uint2 hi = *(const uint2*)(Ap + (r0+gid+8)*64 + kc*16 + 4*l4);
            af[kc][0]=lo.x; af[kc][1]=hi.x; af[kc][2]=lo.y; af[kc][3]=hi.y;
        }
        #pragma unroll
        for (int j=0;j<8;j++){
            #pragma unroll
            for (int kc=0;kc<4;kc++){
                uint2 bb = *(const uint2*)(Bs + (j*8+gid)*80 + kc*16 + 4*l4);
                MMA_F16(c[j][0],c[j][1],c[j][2],c[j][3],
                        af[kc][0],af[kc][1],af[kc][2],af[kc][3],bb.x,bb.y);
            }
        }
    }
    __syncthreads();
    const int r_lo = r0 + gid, r_hi = r_lo + 8;
    #pragma unroll
    for (int j=0;j<8;j++){
        int col = j*8 + 2*l4;
        float b0 = fcb[col], b1 = fcb[col+1];
        Cs[r_lo*69+col  ] = c[j][0] + b0 + g_cf[b*65536 + (s0+r_lo)*64 + col  ];
        Cs[r_lo*69+col+1] = c[j][1] + b1 + g_cf[b*65536 + (s0+r_lo)*64 + col+1];
        Cs[r_hi*69+col  ] = c[j][2] + b0 + g_cf[b*65536 + (s0+r_hi)*64 + col  ];
        Cs[r_hi*69+col+1] = c[j][3] + b1 + g_cf[b*65536 + (s0+r_hi)*64 + col+1];
    }
    __syncthreads();
    for (int rr=0; rr<16; rr++){
        int r = w*16 + rr;
        float v0 = Cs[r*69+lane], v1 = Cs[r*69+lane+32];
        float sm = v0+v1, sq = v0*v0 + v1*v1;
        #pragma unroll
        for (int off=16; off; off>>=1){
            sm += __shfl_xor_sync(0xffffffffu, sm, off);
            sq += __shfl_xor_sync(0xffffffffu, sq, off);
        }
        float mu = sm*(1.f/64.f);
        float var = sq*(1.f/64.f) - mu*mu;
        float rstd = rsqrtf(var + 1e-6f);
        Cs[r*69+lane]    = (v0-mu)*rstd*lng[lane]    + lnb[lane];
        Cs[r*69+lane+32] = (v1-mu)*rstd*lng[lane+32] + lnb[lane+32];
    }
    __syncthreads();
    #pragma unroll
    for (int i=0;i<32;i++){
        int idx = i*256 + tid;
        int cc = idx>>7, sl = idx&127;
        out[(((b<<6)+cc)<<10) + s0 + sl] = Cs[sl*69+cc];
    }
}

// ============================== launcher ===================================
extern "C" void kernel_launch(void* const* d_in, const int* in_sizes, int n_in,
                              void* d_out, int out_size)
{
    const float* x      = (const float*)d_in[0];
    const float* memory = (const float*)d_in[1];
    const float* wb_w   = (const float*)d_in[2];
    const float* wb_b   = (const float*)d_in[3];
    const float* a1_wq  = (const float*)d_in[4];
    const float* a1_bq  = (const float*)d_in[5];
    const float* a1_wk  = (const float*)d_in[6];
    const float* a1_bk  = (const float*)d_in[7];
    const float* a1_wv  = (const float*)d_in[8];
    const float* a1_bv  = (const float*)d_in[9];
    const float* a1_fc  = (const float*)d_in[10];
    const float* a1_fcb = (const float*)d_in[11];
    const float* a1_lng = (const float*)d_in[12];
    const float* a1_lnb = (const float*)d_in[13];
    const float* a2_wq  = (const float*)d_in[14];
    const float* a2_bq  = (const float*)d_in[15];
    const float* a2_wk  = (const float*)d_in[16];
    const float* a2_bk  = (const float*)d_in[17];
    const float* a2_wv  = (const float*)d_in[18];
    const float* a2_bv  = (const float*)d_in[19];
    const float* a2_fc  = (const float*)d_in[20];
    const float* a2_fcb = (const float*)d_in[21];
    const float* a2_lng = (const float*)d_in[22];
    const float* a2_lnb = (const float*)d_in[23];
    float* out = (float*)d_out;

    __half *pq=0, *pk=0, *pv=0;
    cudaGetSymbolAddress((void**)&pq, g_q);
    cudaGetSymbolAddress((void**)&pk, g_k);
    cudaGetSymbolAddress((void**)&pv, g_v);

    const int kcm_smem = 17536*4;          // 70144 B
    const int kd_smem  = 20480*2;          // 40960 B -> 2 CTAs/SM
    const int ke_smem  = 128*69*4;         // 35328 B
    cudaFuncSetAttribute(kCm, cudaFuncAttributeMaxDynamicSharedMemorySize, kcm_smem);
    cudaFuncSetAttribute(kD,  cudaFuncAttributeMaxDynamicSharedMemorySize, kd_smem);
    cudaFuncSetAttribute(kE3, cudaFuncAttributeMaxDynamicSharedMemorySize, ke_smem);

    kA<<<NB, 1024>>>(x, wb_w, wb_b);
    dim3 gP(16, NB);
    kP<<<gP, 256>>>(x);
    kB<<<NB, 512>>>(memory, a1_wq, a1_bq, a1_wk, a1_bk, a1_wv, a1_bv,
                    a1_fc, a1_fcb, a1_lng, a1_lnb);
    dim3 gC(128, 2);
    kCm<<<gC, 256, kcm_smem>>>(a2_wq, a2_wk, a2_wv, a2_bq, a2_bk, a2_bv, pq, pk, pv);
    dim3 gD(8, 4, NB);
    kD<<<gD, 128, kd_smem>>>();
    dim3 gE(8, NB);
    kE3<<<gE, 256, ke_smem>>>(a2_fc, a2_fcb, a2_lng, a2_lnb, out);
}